// round 2
// baseline (speedup 1.0000x reference)
#include <cuda_runtime.h>
#include <cstddef>

#define NATOM 100000
#define NCL   25000
#define EA    600000
#define EC    100000
#define EB    100000
#define HD    128
#define PD    256
#define BN_EPS 1e-5f

// ---------------- scratch (static device memory; no allocs allowed) ----------------
__device__ float g_agg_atom[(size_t)NATOM * HD];   // GINE atom aggregation
__device__ float g_agg_cl[(size_t)NCL * HD];       // GINE cluster aggregation
__device__ float g_aggm_c2a[(size_t)NATOM * HD];   // SAGE c2atom sum
__device__ float g_cnt_c2a[NATOM];
__device__ float g_aggm_a2c[(size_t)NCL * HD];     // SAGE atom2c sum
__device__ float g_cnt_a2c[NCL];
__device__ float g_pre_atom[(size_t)NATOM * PD];   // pre-BN GINE output
__device__ float g_pre_cl[(size_t)NCL * PD];
__device__ float g_S_atom[(size_t)NATOM * PD];     // SAGE output
__device__ float g_S_cl[(size_t)NCL * PD];
__device__ float g_stats_atom[2 * PD];             // colsum, colsumsq
__device__ float g_stats_cl[2 * PD];
__device__ float g_scale_atom[PD];
__device__ float g_shift_atom[PD];
__device__ float g_scale_cl[PD];
__device__ float g_shift_cl[PD];

// ---------------- edge scatter: GINE message relu(x[src]+ea[e]) -> agg[dst] -------
__global__ void gine_scatter(const float* __restrict__ x,
                             const float* __restrict__ ea,
                             const int* __restrict__ ei, int E,
                             float* __restrict__ agg) {
    int warp = (blockIdx.x * blockDim.x + threadIdx.x) >> 5;
    int lane = threadIdx.x & 31;
    if (warp >= E) return;
    int src = ei[warp];
    int dst = ei[E + warp];
    float4 xv = reinterpret_cast<const float4*>(x + (size_t)src * HD)[lane];
    float4 ev = reinterpret_cast<const float4*>(ea + (size_t)warp * HD)[lane];
    float m0 = fmaxf(xv.x + ev.x, 0.0f);
    float m1 = fmaxf(xv.y + ev.y, 0.0f);
    float m2 = fmaxf(xv.z + ev.z, 0.0f);
    float m3 = fmaxf(xv.w + ev.w, 0.0f);
    float* a = agg + (size_t)dst * HD + lane * 4;
    atomicAdd(a + 0, m0);
    atomicAdd(a + 1, m1);
    atomicAdd(a + 2, m2);
    atomicAdd(a + 3, m3);
}

// ---------------- edge scatter: SAGE sum x_src[src] -> aggm[dst], count -----------
__global__ void sage_scatter(const float* __restrict__ xsrc,
                             const int* __restrict__ ei, int E,
                             float* __restrict__ aggm, float* __restrict__ cnt) {
    int warp = (blockIdx.x * blockDim.x + threadIdx.x) >> 5;
    int lane = threadIdx.x & 31;
    if (warp >= E) return;
    int src = ei[warp];
    int dst = ei[E + warp];
    float4 xv = reinterpret_cast<const float4*>(xsrc + (size_t)src * HD)[lane];
    float* a = aggm + (size_t)dst * HD + lane * 4;
    atomicAdd(a + 0, xv.x);
    atomicAdd(a + 1, xv.y);
    atomicAdd(a + 2, xv.z);
    atomicAdd(a + 3, xv.w);
    if (lane == 0) atomicAdd(&cnt[dst], 1.0f);
}

// ---------------- column stats (sum, sumsq) for BatchNorm -------------------------
__global__ void colstats(const float* __restrict__ pre, int M,
                         float* __restrict__ stats) {
    const int RPB = 256;
    int c = threadIdx.x;            // 256 threads = 256 columns
    int r0 = blockIdx.x * RPB;
    int r1 = min(r0 + RPB, M);
    float s = 0.0f, ss = 0.0f;
    for (int r = r0; r < r1; r++) {
        float v = pre[(size_t)r * PD + c];
        s += v;
        ss += v * v;
    }
    atomicAdd(&stats[c], s);
    atomicAdd(&stats[PD + c], ss);
}

__global__ void bn_finalize(const float* __restrict__ stats,
                            const float* __restrict__ gamma,
                            const float* __restrict__ beta,
                            float invM,
                            float* __restrict__ scale,
                            float* __restrict__ shift) {
    int c = threadIdx.x;
    float mu = stats[c] * invM;
    float var = stats[PD + c] * invM - mu * mu;
    float sc = gamma[c] * rsqrtf(var + BN_EPS);
    scale[c] = sc;
    shift[c] = beta[c] - mu * sc;
}

// ---------------- unified tiled GEMM with fused A-transforms ----------------------
// mode 0 (GINE):  A[r,k] = (1+eps)*A0[r,k] + A1[r,k]                 (K=128)
// mode 1 (SAGE):  A[r,k] = k<128 ? A0[r,k]/max(cnt[r],1) : A1[r,k-128] (K=256)
//                 B rows: k<128 -> B0 (Wl), else B1 (Wr); bias0+bias1
// mode 2 (MERGE): A[r,k] = relu(A0[r,k]*scale[k]+shift[k]) + A1[r,k] (K=256)
template <int K, int BN>
__global__ __launch_bounds__(256)
void gemm_kernel(int mode, int M,
                 const float* __restrict__ A0, const float* __restrict__ A1,
                 const float* __restrict__ aux0, const float* __restrict__ aux1,
                 const float* __restrict__ B0, const float* __restrict__ B1, int ldb,
                 const float* __restrict__ bias0, const float* __restrict__ bias1,
                 const float* __restrict__ epsPtr,
                 float* __restrict__ C, int ldc) {
    constexpr int BM = 32;
    constexpr int CPT = BN / 32;
    extern __shared__ float sm[];
    float* As = sm;              // [BM][K]
    float* Bs = sm + BM * K;     // [K][BN]

    const int tid = threadIdx.x;
    const int m0 = blockIdx.x * BM;
    const int bn0 = blockIdx.y * BN;

    // load B tile
    for (int idx = tid; idx < K * BN; idx += 256) {
        int k = idx / BN;
        int n = bn0 + (idx - k * BN);
        float bv;
        if (mode == 1 && k >= 128)
            bv = B1[(size_t)(k - 128) * ldb + n];
        else
            bv = B0[(size_t)k * ldb + n];
        Bs[idx] = bv;
    }

    float ef = 1.0f;
    if (mode == 0) ef = 1.0f + *epsPtr;

    // load + transform A tile
    for (int idx = tid; idx < BM * K; idx += 256) {
        int r = idx / K;
        int k = idx - r * K;
        int gr = m0 + r;
        float v = 0.0f;
        if (gr < M) {
            if (mode == 0) {
                v = ef * A0[(size_t)gr * K + k] + A1[(size_t)gr * K + k];
            } else if (mode == 1) {
                if (k < 128)
                    v = __fdividef(A0[(size_t)gr * 128 + k], fmaxf(aux0[gr], 1.0f));
                else
                    v = A1[(size_t)gr * 128 + (k - 128)];
            } else {
                float p = A0[(size_t)gr * 256 + k];
                v = fmaxf(fmaf(p, aux0[k], aux1[k]), 0.0f) + A1[(size_t)gr * 256 + k];
            }
        }
        As[idx] = v;
    }
    __syncthreads();

    const int tcol = tid & 31;
    const int trow = tid >> 5;  // 0..7

    float acc[4][CPT];
#pragma unroll
    for (int ri = 0; ri < 4; ri++)
#pragma unroll
        for (int ci = 0; ci < CPT; ci++) acc[ri][ci] = 0.0f;

#pragma unroll 4
    for (int k = 0; k < K; k++) {
        float b[CPT];
#pragma unroll
        for (int ci = 0; ci < CPT; ci++) b[ci] = Bs[k * BN + tcol + 32 * ci];
#pragma unroll
        for (int ri = 0; ri < 4; ri++) {
            float a = As[(trow + 8 * ri) * K + k];
#pragma unroll
            for (int ci = 0; ci < CPT; ci++)
                acc[ri][ci] = fmaf(a, b[ci], acc[ri][ci]);
        }
    }

#pragma unroll
    for (int ri = 0; ri < 4; ri++) {
        int gr = m0 + trow + 8 * ri;
        if (gr >= M) continue;
#pragma unroll
        for (int ci = 0; ci < CPT; ci++) {
            int n = bn0 + tcol + 32 * ci;
            float o = acc[ri][ci] + bias0[n];
            if (bias1) o += bias1[n];
            C[(size_t)gr * ldc + n] = o;
        }
    }
}

// -----------------------------------------------------------------------------------
extern "C" void kernel_launch(void* const* d_in, const int* in_sizes, int n_in,
                              void* d_out, int out_size) {
    // ---- input mapping (auto-detect order) ----
    const float* x         = (const float*)d_in[0];
    const float* edge_attr = (const float*)d_in[1];
    const float* x_cl      = (const float*)d_in[2];
    const float* c2c_ea    = (const float*)d_in[3];

    const int *ei_a, *ei_c2c, *ei_a2c, *ei_c2a;
    const float *atom_eps, *atom_W, *atom_b, *atom_gamma, *atom_beta;
    const float *cl_eps, *cl_W, *cl_b, *cl_gamma, *cl_beta;
    const float *a2c_Wl, *a2c_bl, *a2c_Wr, *a2c_br;
    const float *c2a_Wl, *c2a_bl, *c2a_Wr, *c2a_br;
    const float *merge_atom_W, *merge_atom_b, *merge_cl_W, *merge_cl_b;

    int pbase, ebase;
    if (in_sizes[4] == 2 * EA) {  // dict order: edge indices at 4..7, params at 8..29
        ebase = 4; pbase = 8;
    } else {                      // signature order: params at 4..25, edges at 26..29
        pbase = 4; ebase = 26;
    }
    ei_a   = (const int*)d_in[ebase + 0];
    ei_c2c = (const int*)d_in[ebase + 1];
    ei_a2c = (const int*)d_in[ebase + 2];
    ei_c2a = (const int*)d_in[ebase + 3];

    atom_eps   = (const float*)d_in[pbase + 0];
    atom_W     = (const float*)d_in[pbase + 1];
    atom_b     = (const float*)d_in[pbase + 2];
    atom_gamma = (const float*)d_in[pbase + 3];
    atom_beta  = (const float*)d_in[pbase + 4];
    cl_eps     = (const float*)d_in[pbase + 5];
    cl_W       = (const float*)d_in[pbase + 6];
    cl_b       = (const float*)d_in[pbase + 7];
    cl_gamma   = (const float*)d_in[pbase + 8];
    cl_beta    = (const float*)d_in[pbase + 9];
    a2c_Wl     = (const float*)d_in[pbase + 10];
    a2c_bl     = (const float*)d_in[pbase + 11];
    a2c_Wr     = (const float*)d_in[pbase + 12];
    a2c_br     = (const float*)d_in[pbase + 13];
    c2a_Wl     = (const float*)d_in[pbase + 14];
    c2a_bl     = (const float*)d_in[pbase + 15];
    c2a_Wr     = (const float*)d_in[pbase + 16];
    c2a_br     = (const float*)d_in[pbase + 17];
    merge_atom_W = (const float*)d_in[pbase + 18];
    merge_atom_b = (const float*)d_in[pbase + 19];
    merge_cl_W   = (const float*)d_in[pbase + 20];
    merge_cl_b   = (const float*)d_in[pbase + 21];

    float* out = (float*)d_out;

    // ---- scratch addresses ----
    float *p_agg_atom, *p_agg_cl, *p_aggm_c2a, *p_cnt_c2a, *p_aggm_a2c, *p_cnt_a2c;
    float *p_pre_atom, *p_pre_cl, *p_S_atom, *p_S_cl;
    float *p_stats_atom, *p_stats_cl, *p_scale_atom, *p_shift_atom, *p_scale_cl, *p_shift_cl;
    cudaGetSymbolAddress((void**)&p_agg_atom, g_agg_atom);
    cudaGetSymbolAddress((void**)&p_agg_cl, g_agg_cl);
    cudaGetSymbolAddress((void**)&p_aggm_c2a, g_aggm_c2a);
    cudaGetSymbolAddress((void**)&p_cnt_c2a, g_cnt_c2a);
    cudaGetSymbolAddress((void**)&p_aggm_a2c, g_aggm_a2c);
    cudaGetSymbolAddress((void**)&p_cnt_a2c, g_cnt_a2c);
    cudaGetSymbolAddress((void**)&p_pre_atom, g_pre_atom);
    cudaGetSymbolAddress((void**)&p_pre_cl, g_pre_cl);
    cudaGetSymbolAddress((void**)&p_S_atom, g_S_atom);
    cudaGetSymbolAddress((void**)&p_S_cl, g_S_cl);
    cudaGetSymbolAddress((void**)&p_stats_atom, g_stats_atom);
    cudaGetSymbolAddress((void**)&p_stats_cl, g_stats_cl);
    cudaGetSymbolAddress((void**)&p_scale_atom, g_scale_atom);
    cudaGetSymbolAddress((void**)&p_shift_atom, g_shift_atom);
    cudaGetSymbolAddress((void**)&p_scale_cl, g_scale_cl);
    cudaGetSymbolAddress((void**)&p_shift_cl, g_shift_cl);

    // ---- zero the accumulation scratch ----
    cudaMemsetAsync(p_agg_atom, 0, (size_t)NATOM * HD * 4, 0);
    cudaMemsetAsync(p_agg_cl, 0, (size_t)NCL * HD * 4, 0);
    cudaMemsetAsync(p_aggm_c2a, 0, (size_t)NATOM * HD * 4, 0);
    cudaMemsetAsync(p_cnt_c2a, 0, (size_t)NATOM * 4, 0);
    cudaMemsetAsync(p_aggm_a2c, 0, (size_t)NCL * HD * 4, 0);
    cudaMemsetAsync(p_cnt_a2c, 0, (size_t)NCL * 4, 0);
    cudaMemsetAsync(p_stats_atom, 0, 2 * PD * 4, 0);
    cudaMemsetAsync(p_stats_cl, 0, 2 * PD * 4, 0);

    // ---- dynamic smem attributes for the two GEMM instantiations ----
    const int SMEM_A = (32 * 128 + 128 * 256) * 4;   // 147456 B  (<128,256>)
    const int SMEM_B = (32 * 256 + 256 * 128) * 4;   // 163840 B  (<256,128>)
    cudaFuncSetAttribute((const void*)gemm_kernel<128, 256>,
                         cudaFuncAttributeMaxDynamicSharedMemorySize, SMEM_A);
    cudaFuncSetAttribute((const void*)gemm_kernel<256, 128>,
                         cudaFuncAttributeMaxDynamicSharedMemorySize, SMEM_B);

    // ---- scatter passes ----
    gine_scatter<<<(EA * 32 + 255) / 256, 256>>>(x, edge_attr, ei_a, EA, p_agg_atom);
    gine_scatter<<<(EC * 32 + 255) / 256, 256>>>(x_cl, c2c_ea, ei_c2c, EC, p_agg_cl);
    sage_scatter<<<(EB * 32 + 255) / 256, 256>>>(x, ei_a2c, EB, p_aggm_a2c, p_cnt_a2c);
    sage_scatter<<<(EB * 32 + 255) / 256, 256>>>(x_cl, ei_c2a, EB, p_aggm_c2a, p_cnt_c2a);

    const int GA = (NATOM + 31) / 32;   // 3125
    const int GC = (NCL + 31) / 32;     // 782

    // ---- GINE GEMMs (pre-BN) ----
    gemm_kernel<128, 256><<<dim3(GA, 1), 256, SMEM_A>>>(
        0, NATOM, x, p_agg_atom, nullptr, nullptr,
        atom_W, nullptr, 256, atom_b, nullptr, atom_eps, p_pre_atom, 256);
    gemm_kernel<128, 256><<<dim3(GC, 1), 256, SMEM_A>>>(
        0, NCL, x_cl, p_agg_cl, nullptr, nullptr,
        cl_W, nullptr, 256, cl_b, nullptr, cl_eps, p_pre_cl, 256);

    // ---- BN stats ----
    colstats<<<(NATOM + 255) / 256, 256>>>(p_pre_atom, NATOM, p_stats_atom);
    colstats<<<(NCL + 255) / 256, 256>>>(p_pre_cl, NCL, p_stats_cl);
    bn_finalize<<<1, 256>>>(p_stats_atom, atom_gamma, atom_beta, 1.0f / NATOM,
                            p_scale_atom, p_shift_atom);
    bn_finalize<<<1, 256>>>(p_stats_cl, cl_gamma, cl_beta, 1.0f / NCL,
                            p_scale_cl, p_shift_cl);

    // ---- SAGE GEMMs:  [mean | x_dst] @ [Wl ; Wr] + bl + br ----
    gemm_kernel<256, 128><<<dim3(GA, 2), 256, SMEM_B>>>(
        1, NATOM, p_aggm_c2a, x, p_cnt_c2a, nullptr,
        c2a_Wl, c2a_Wr, 256, c2a_bl, c2a_br, nullptr, p_S_atom, 256);
    gemm_kernel<256, 128><<<dim3(GC, 2), 256, SMEM_B>>>(
        1, NCL, p_aggm_a2c, x_cl, p_cnt_a2c, nullptr,
        a2c_Wl, a2c_Wr, 256, a2c_bl, a2c_br, nullptr, p_S_cl, 256);

    // ---- merge GEMMs with fused BN+ReLU+residual: writes final output ----
    gemm_kernel<256, 128><<<dim3(GA, 1), 256, SMEM_B>>>(
        2, NATOM, p_pre_atom, p_S_atom, p_scale_atom, p_shift_atom,
        merge_atom_W, nullptr, 128, merge_atom_b, nullptr, nullptr, out, 128);
    gemm_kernel<256, 128><<<dim3(GC, 1), 256, SMEM_B>>>(
        2, NCL, p_pre_cl, p_S_cl, p_scale_cl, p_shift_cl,
        merge_cl_W, nullptr, 128, merge_cl_b, nullptr, nullptr,
        out + (size_t)NATOM * HD, 128);
}

// round 3
// speedup vs baseline: 2.3833x; 2.3833x over previous
#include <cuda_runtime.h>
#include <cstddef>

#define NATOM 100000
#define NCL   25000
#define EA    600000
#define EC    100000
#define EB    100000
#define HD    128
#define PD    256
#define BN_EPS 1e-5f

typedef unsigned long long ull;

// ---------------- scratch (static device memory; no allocs allowed) ----------------
__device__ float g_agg_atom[(size_t)NATOM * HD];
__device__ float g_agg_cl[(size_t)NCL * HD];
__device__ float g_aggm_c2a[(size_t)NATOM * HD];
__device__ float g_cnt_c2a[NATOM];
__device__ float g_aggm_a2c[(size_t)NCL * HD];
__device__ float g_cnt_a2c[NCL];
__device__ float g_pre_atom[(size_t)NATOM * PD];
__device__ float g_pre_cl[(size_t)NCL * PD];
__device__ float g_S_atom[(size_t)NATOM * PD];
__device__ float g_S_cl[(size_t)NCL * PD];
__device__ float g_stats_atom[2 * PD];
__device__ float g_stats_cl[2 * PD];
__device__ float g_scale_atom[PD];
__device__ float g_shift_atom[PD];
__device__ float g_scale_cl[PD];
__device__ float g_shift_cl[PD];

// ---------------- packed f32x2 helpers (sm_103a FFMA2) ----------------------------
__device__ __forceinline__ ull pack2(float x, float y) {
    ull d;
    asm("mov.b64 %0, {%1, %2};" : "=l"(d) : "f"(x), "f"(y));
    return d;
}
__device__ __forceinline__ void unpack2(float& x, float& y, ull v) {
    asm("mov.b64 {%0, %1}, %2;" : "=f"(x), "=f"(y) : "l"(v));
}
__device__ __forceinline__ ull ffma2(ull a, ull b, ull c) {
    ull d;
    asm("fma.rn.f32x2 %0, %1, %2, %3;" : "=l"(d) : "l"(a), "l"(b), "l"(c));
    return d;
}

// ---------------- edge scatter: GINE message relu(x[src]+ea[e]) -> agg[dst] -------
__global__ void gine_scatter(const float* __restrict__ x,
                             const float* __restrict__ ea,
                             const int* __restrict__ ei, int E,
                             float* __restrict__ agg) {
    int warp = (blockIdx.x * blockDim.x + threadIdx.x) >> 5;
    int lane = threadIdx.x & 31;
    if (warp >= E) return;
    int src = ei[warp];
    int dst = ei[E + warp];
    float4 xv = reinterpret_cast<const float4*>(x + (size_t)src * HD)[lane];
    float4 ev = reinterpret_cast<const float4*>(ea + (size_t)warp * HD)[lane];
    float m0 = fmaxf(xv.x + ev.x, 0.0f);
    float m1 = fmaxf(xv.y + ev.y, 0.0f);
    float m2 = fmaxf(xv.z + ev.z, 0.0f);
    float m3 = fmaxf(xv.w + ev.w, 0.0f);
    float* a = agg + (size_t)dst * HD + lane * 4;
    atomicAdd(a + 0, m0);
    atomicAdd(a + 1, m1);
    atomicAdd(a + 2, m2);
    atomicAdd(a + 3, m3);
}

// ---------------- edge scatter: SAGE sum x_src[src] -> aggm[dst], count -----------
__global__ void sage_scatter(const float* __restrict__ xsrc,
                             const int* __restrict__ ei, int E,
                             float* __restrict__ aggm, float* __restrict__ cnt) {
    int warp = (blockIdx.x * blockDim.x + threadIdx.x) >> 5;
    int lane = threadIdx.x & 31;
    if (warp >= E) return;
    int src = ei[warp];
    int dst = ei[E + warp];
    float4 xv = reinterpret_cast<const float4*>(xsrc + (size_t)src * HD)[lane];
    float* a = aggm + (size_t)dst * HD + lane * 4;
    atomicAdd(a + 0, xv.x);
    atomicAdd(a + 1, xv.y);
    atomicAdd(a + 2, xv.z);
    atomicAdd(a + 3, xv.w);
    if (lane == 0) atomicAdd(&cnt[dst], 1.0f);
}

// ---------------- column stats (sum, sumsq) for BatchNorm -------------------------
__global__ void colstats(const float* __restrict__ pre, int M,
                         float* __restrict__ stats) {
    const int RPB = 256;
    int c = threadIdx.x;
    int r0 = blockIdx.x * RPB;
    int r1 = min(r0 + RPB, M);
    float s = 0.0f, ss = 0.0f;
    for (int r = r0; r < r1; r++) {
        float v = pre[(size_t)r * PD + c];
        s += v;
        ss += v * v;
    }
    atomicAdd(&stats[c], s);
    atomicAdd(&stats[PD + c], ss);
}

__global__ void bn_finalize(const float* __restrict__ stats,
                            const float* __restrict__ gamma,
                            const float* __restrict__ beta,
                            float invM,
                            float* __restrict__ scale,
                            float* __restrict__ shift) {
    int c = threadIdx.x;
    float mu = stats[c] * invM;
    float var = stats[PD + c] * invM - mu * mu;
    float sc = gamma[c] * rsqrtf(var + BN_EPS);
    scale[c] = sc;
    shift[c] = beta[c] - mu * sc;
}

// ---------------- 128x128 tiled GEMM, 8x8 micro-tiles, packed FFMA2 ---------------
// mode 0 (GINE):  A[r,k] = (1+eps)*A0[r,k] + A1[r,k]                       (K=128)
// mode 1 (SAGE):  A[r,k] = k<128 ? A0[r,k]/max(cnt[r],1) : A1[r,k-128]     (K=256)
//                 B rows: k<128 -> B0 (Wl), else B1 (Wr); bias0+bias1
// mode 2 (MERGE): A[r,k] = relu(A0[r,k]*scale[k]+shift[k]) + A1[r,k]       (K=256)
template <int K>
__global__ __launch_bounds__(256)
void gemm128(int mode, int M,
             const float* __restrict__ A0, const float* __restrict__ A1,
             const float* __restrict__ aux0, const float* __restrict__ aux1,
             const float* __restrict__ B0, const float* __restrict__ B1, int ldb,
             const float* __restrict__ bias0, const float* __restrict__ bias1,
             const float* __restrict__ epsPtr,
             float* __restrict__ C, int ldc) {
    constexpr int KC = 128;
    constexpr int BM = 128;
    constexpr int BN = 128;
    extern __shared__ float sm[];
    float* As = sm;                 // [KC][BM]  (k-major, m contiguous)
    float* Bs = sm + KC * BM;       // [KC][BN]

    const int tid = threadIdx.x;
    const int tx = tid & 15;        // n-group: cols tx*8..tx*8+7
    const int ty = tid >> 4;        // m-group: rows ty*8..ty*8+7
    const int m0 = blockIdx.x * BM;
    const int n0g = blockIdx.y * BN;

    float ef = 1.0f;
    if (mode == 0) ef += *epsPtr;

    ull acc[8][4];
#pragma unroll
    for (int ri = 0; ri < 8; ri++)
#pragma unroll
        for (int ci = 0; ci < 4; ci++) acc[ri][ci] = 0ULL;

    for (int kk = 0; kk < K; kk += KC) {
        // ---- load B tile: Bs[k][n] ----
#pragma unroll
        for (int it = 0; it < 16; it++) {
            int idx = tid + it * 256;      // 0..4095 float4s
            int k = idx >> 5;              // 0..127
            int nq = idx & 31;
            int gk = kk + k;
            const float* brow;
            if (mode == 1 && gk >= 128)
                brow = B1 + (size_t)(gk - 128) * ldb;
            else
                brow = B0 + (size_t)gk * ldb;
            reinterpret_cast<float4*>(Bs)[idx] =
                *reinterpret_cast<const float4*>(brow + n0g + nq * 4);
        }
        // ---- load + transform A tile: As[k][m] ----
#pragma unroll
        for (int it = 0; it < 16; it++) {
            int idx = tid + it * 256;      // 0..4095
            int r = idx & 127;
            int kq = idx >> 7;             // 0..31
            int gr = m0 + r;
            int gk = kk + kq * 4;
            float4 v = make_float4(0.f, 0.f, 0.f, 0.f);
            if (gr < M) {
                if (mode == 0) {
                    float4 a = *reinterpret_cast<const float4*>(A0 + (size_t)gr * K + gk);
                    float4 g = *reinterpret_cast<const float4*>(A1 + (size_t)gr * K + gk);
                    v.x = fmaf(ef, a.x, g.x);
                    v.y = fmaf(ef, a.y, g.y);
                    v.z = fmaf(ef, a.z, g.z);
                    v.w = fmaf(ef, a.w, g.w);
                } else if (mode == 1) {
                    if (gk < 128) {
                        float4 a = *reinterpret_cast<const float4*>(A0 + (size_t)gr * 128 + gk);
                        float inv = __frcp_rn(fmaxf(aux0[gr], 1.0f));
                        v.x = a.x * inv; v.y = a.y * inv; v.z = a.z * inv; v.w = a.w * inv;
                    } else {
                        v = *reinterpret_cast<const float4*>(A1 + (size_t)gr * 128 + (gk - 128));
                    }
                } else {
                    float4 p = *reinterpret_cast<const float4*>(A0 + (size_t)gr * 256 + gk);
                    float4 q = *reinterpret_cast<const float4*>(A1 + (size_t)gr * 256 + gk);
                    float4 s = *reinterpret_cast<const float4*>(aux0 + gk);
                    float4 h = *reinterpret_cast<const float4*>(aux1 + gk);
                    v.x = fmaxf(fmaf(p.x, s.x, h.x), 0.f) + q.x;
                    v.y = fmaxf(fmaf(p.y, s.y, h.y), 0.f) + q.y;
                    v.z = fmaxf(fmaf(p.z, s.z, h.z), 0.f) + q.z;
                    v.w = fmaxf(fmaf(p.w, s.w, h.w), 0.f) + q.w;
                }
            }
            As[(kq * 4 + 0) * BM + r] = v.x;
            As[(kq * 4 + 1) * BM + r] = v.y;
            As[(kq * 4 + 2) * BM + r] = v.z;
            As[(kq * 4 + 3) * BM + r] = v.w;
        }
        __syncthreads();

        const float4* As4 = reinterpret_cast<const float4*>(As);
        const float4* Bs4 = reinterpret_cast<const float4*>(Bs);
#pragma unroll 8
        for (int k = 0; k < KC; k++) {
            float4 a0 = As4[k * 32 + ty * 2];
            float4 a1 = As4[k * 32 + ty * 2 + 1];
            float4 b0 = Bs4[k * 32 + tx * 2];
            float4 b1 = Bs4[k * 32 + tx * 2 + 1];
            ull bp0 = pack2(b0.x, b0.y);
            ull bp1 = pack2(b0.z, b0.w);
            ull bp2 = pack2(b1.x, b1.y);
            ull bp3 = pack2(b1.z, b1.w);
            float av[8] = {a0.x, a0.y, a0.z, a0.w, a1.x, a1.y, a1.z, a1.w};
#pragma unroll
            for (int ri = 0; ri < 8; ri++) {
                ull ap = pack2(av[ri], av[ri]);
                acc[ri][0] = ffma2(ap, bp0, acc[ri][0]);
                acc[ri][1] = ffma2(ap, bp1, acc[ri][1]);
                acc[ri][2] = ffma2(ap, bp2, acc[ri][2]);
                acc[ri][3] = ffma2(ap, bp3, acc[ri][3]);
            }
        }
        __syncthreads();
    }

    // ---- epilogue: unpack, add bias, store ----
    float bias[8];
#pragma unroll
    for (int ci = 0; ci < 8; ci++) {
        int n = n0g + tx * 8 + ci;
        float b = bias0[n];
        if (bias1) b += bias1[n];
        bias[ci] = b;
    }
#pragma unroll
    for (int ri = 0; ri < 8; ri++) {
        int gr = m0 + ty * 8 + ri;
        if (gr >= M) continue;
        float o[8];
#pragma unroll
        for (int ci = 0; ci < 4; ci++)
            unpack2(o[2 * ci], o[2 * ci + 1], acc[ri][ci]);
#pragma unroll
        for (int ci = 0; ci < 8; ci++) o[ci] += bias[ci];
        float* crow = C + (size_t)gr * ldc + n0g + tx * 8;
        *reinterpret_cast<float4*>(crow) = make_float4(o[0], o[1], o[2], o[3]);
        *reinterpret_cast<float4*>(crow + 4) = make_float4(o[4], o[5], o[6], o[7]);
    }
}

// -----------------------------------------------------------------------------------
extern "C" void kernel_launch(void* const* d_in, const int* in_sizes, int n_in,
                              void* d_out, int out_size) {
    const float* x         = (const float*)d_in[0];
    const float* edge_attr = (const float*)d_in[1];
    const float* x_cl      = (const float*)d_in[2];
    const float* c2c_ea    = (const float*)d_in[3];

    int pbase, ebase;
    if (in_sizes[4] == 2 * EA) { ebase = 4; pbase = 8; }
    else                       { pbase = 4; ebase = 26; }

    const int* ei_a   = (const int*)d_in[ebase + 0];
    const int* ei_c2c = (const int*)d_in[ebase + 1];
    const int* ei_a2c = (const int*)d_in[ebase + 2];
    const int* ei_c2a = (const int*)d_in[ebase + 3];

    const float* atom_eps   = (const float*)d_in[pbase + 0];
    const float* atom_W     = (const float*)d_in[pbase + 1];
    const float* atom_b     = (const float*)d_in[pbase + 2];
    const float* atom_gamma = (const float*)d_in[pbase + 3];
    const float* atom_beta  = (const float*)d_in[pbase + 4];
    const float* cl_eps     = (const float*)d_in[pbase + 5];
    const float* cl_W       = (const float*)d_in[pbase + 6];
    const float* cl_b       = (const float*)d_in[pbase + 7];
    const float* cl_gamma   = (const float*)d_in[pbase + 8];
    const float* cl_beta    = (const float*)d_in[pbase + 9];
    const float* a2c_Wl     = (const float*)d_in[pbase + 10];
    const float* a2c_bl     = (const float*)d_in[pbase + 11];
    const float* a2c_Wr     = (const float*)d_in[pbase + 12];
    const float* a2c_br     = (const float*)d_in[pbase + 13];
    const float* c2a_Wl     = (const float*)d_in[pbase + 14];
    const float* c2a_bl     = (const float*)d_in[pbase + 15];
    const float* c2a_Wr     = (const float*)d_in[pbase + 16];
    const float* c2a_br     = (const float*)d_in[pbase + 17];
    const float* merge_atom_W = (const float*)d_in[pbase + 18];
    const float* merge_atom_b = (const float*)d_in[pbase + 19];
    const float* merge_cl_W   = (const float*)d_in[pbase + 20];
    const float* merge_cl_b   = (const float*)d_in[pbase + 21];

    float* out = (float*)d_out;

    float *p_agg_atom, *p_agg_cl, *p_aggm_c2a, *p_cnt_c2a, *p_aggm_a2c, *p_cnt_a2c;
    float *p_pre_atom, *p_pre_cl, *p_S_atom, *p_S_cl;
    float *p_stats_atom, *p_stats_cl, *p_scale_atom, *p_shift_atom, *p_scale_cl, *p_shift_cl;
    cudaGetSymbolAddress((void**)&p_agg_atom, g_agg_atom);
    cudaGetSymbolAddress((void**)&p_agg_cl, g_agg_cl);
    cudaGetSymbolAddress((void**)&p_aggm_c2a, g_aggm_c2a);
    cudaGetSymbolAddress((void**)&p_cnt_c2a, g_cnt_c2a);
    cudaGetSymbolAddress((void**)&p_aggm_a2c, g_aggm_a2c);
    cudaGetSymbolAddress((void**)&p_cnt_a2c, g_cnt_a2c);
    cudaGetSymbolAddress((void**)&p_pre_atom, g_pre_atom);
    cudaGetSymbolAddress((void**)&p_pre_cl, g_pre_cl);
    cudaGetSymbolAddress((void**)&p_S_atom, g_S_atom);
    cudaGetSymbolAddress((void**)&p_S_cl, g_S_cl);
    cudaGetSymbolAddress((void**)&p_stats_atom, g_stats_atom);
    cudaGetSymbolAddress((void**)&p_stats_cl, g_stats_cl);
    cudaGetSymbolAddress((void**)&p_scale_atom, g_scale_atom);
    cudaGetSymbolAddress((void**)&p_shift_atom, g_shift_atom);
    cudaGetSymbolAddress((void**)&p_scale_cl, g_scale_cl);
    cudaGetSymbolAddress((void**)&p_shift_cl, g_shift_cl);

    cudaMemsetAsync(p_agg_atom, 0, (size_t)NATOM * HD * 4, 0);
    cudaMemsetAsync(p_agg_cl, 0, (size_t)NCL * HD * 4, 0);
    cudaMemsetAsync(p_aggm_c2a, 0, (size_t)NATOM * HD * 4, 0);
    cudaMemsetAsync(p_cnt_c2a, 0, (size_t)NATOM * 4, 0);
    cudaMemsetAsync(p_aggm_a2c, 0, (size_t)NCL * HD * 4, 0);
    cudaMemsetAsync(p_cnt_a2c, 0, (size_t)NCL * 4, 0);
    cudaMemsetAsync(p_stats_atom, 0, 2 * PD * 4, 0);
    cudaMemsetAsync(p_stats_cl, 0, 2 * PD * 4, 0);

    const int SMEM = 2 * 128 * 128 * 4;  // 131072 B
    cudaFuncSetAttribute((const void*)gemm128<128>,
                         cudaFuncAttributeMaxDynamicSharedMemorySize, SMEM);
    cudaFuncSetAttribute((const void*)gemm128<256>,
                         cudaFuncAttributeMaxDynamicSharedMemorySize, SMEM);

    // ---- scatter passes ----
    gine_scatter<<<(EA * 32 + 255) / 256, 256>>>(x, edge_attr, ei_a, EA, p_agg_atom);
    gine_scatter<<<(EC * 32 + 255) / 256, 256>>>(x_cl, c2c_ea, ei_c2c, EC, p_agg_cl);
    sage_scatter<<<(EB * 32 + 255) / 256, 256>>>(x, ei_a2c, EB, p_aggm_a2c, p_cnt_a2c);
    sage_scatter<<<(EB * 32 + 255) / 256, 256>>>(x_cl, ei_c2a, EB, p_aggm_c2a, p_cnt_c2a);

    const int GA = (NATOM + 127) / 128;  // 782
    const int GC = (NCL + 127) / 128;    // 196

    // ---- GINE GEMMs (pre-BN): [M,128] @ [128,256] ----
    gemm128<128><<<dim3(GA, 2), 256, SMEM>>>(
        0, NATOM, x, p_agg_atom, nullptr, nullptr,
        atom_W, nullptr, 256, atom_b, nullptr, atom_eps, p_pre_atom, 256);
    gemm128<128><<<dim3(GC, 2), 256, SMEM>>>(
        0, NCL, x_cl, p_agg_cl, nullptr, nullptr,
        cl_W, nullptr, 256, cl_b, nullptr, cl_eps, p_pre_cl, 256);

    // ---- BN stats ----
    colstats<<<(NATOM + 255) / 256, 256>>>(p_pre_atom, NATOM, p_stats_atom);
    colstats<<<(NCL + 255) / 256, 256>>>(p_pre_cl, NCL, p_stats_cl);
    bn_finalize<<<1, 256>>>(p_stats_atom, atom_gamma, atom_beta, 1.0f / NATOM,
                            p_scale_atom, p_shift_atom);
    bn_finalize<<<1, 256>>>(p_stats_cl, cl_gamma, cl_beta, 1.0f / NCL,
                            p_scale_cl, p_shift_cl);

    // ---- SAGE GEMMs: [mean | x_dst] @ [Wl ; Wr] + bl + br  -> [M,256] ----
    gemm128<256><<<dim3(GA, 2), 256, SMEM>>>(
        1, NATOM, p_aggm_c2a, x, p_cnt_c2a, nullptr,
        c2a_Wl, c2a_Wr, 256, c2a_bl, c2a_br, nullptr, p_S_atom, 256);
    gemm128<256><<<dim3(GC, 2), 256, SMEM>>>(
        1, NCL, p_aggm_a2c, x_cl, p_cnt_a2c, nullptr,
        a2c_Wl, a2c_Wr, 256, a2c_bl, a2c_br, nullptr, p_S_cl, 256);

    // ---- merge GEMMs (fused BN+ReLU+residual) -> final output [M,128] ----
    gemm128<256><<<dim3(GA, 1), 256, SMEM>>>(
        2, NATOM, p_pre_atom, p_S_atom, p_scale_atom, p_shift_atom,
        merge_atom_W, nullptr, 128, merge_atom_b, nullptr, nullptr, out, 128);
    gemm128<256><<<dim3(GC, 1), 256, SMEM>>>(
        2, NCL, p_pre_cl, p_S_cl, p_scale_cl, p_shift_cl,
        merge_cl_W, nullptr, 128, merge_cl_b, nullptr, nullptr,
        out + (size_t)NATOM * HD, 128);
}

// round 5
// speedup vs baseline: 3.4180x; 1.4342x over previous
#include <cuda_runtime.h>
#include <cuda_bf16.h>
#include <cstdint>
#include <cstddef>

#define NATOM 100000
#define NCL   25000
#define EA    600000
#define EC    100000
#define EB    100000
#define HD    128
#define PD    256
#define BN_EPS 1e-5f

// ---------------- scratch (static device memory; no allocs allowed) ----------------
__device__ float g_agg_atom[(size_t)NATOM * HD];
__device__ float g_agg_cl[(size_t)NCL * HD];
__device__ float g_aggm_c2a[(size_t)NATOM * HD];
__device__ float g_cnt_c2a[NATOM];
__device__ float g_aggm_a2c[(size_t)NCL * HD];
__device__ float g_cnt_a2c[NCL];
__device__ float g_pre_atom[(size_t)NATOM * PD];
__device__ float g_pre_cl[(size_t)NCL * PD];
__device__ float g_S_atom[(size_t)NATOM * PD];
__device__ float g_S_cl[(size_t)NCL * PD];
__device__ float g_stats_atom[2 * PD];
__device__ float g_stats_cl[2 * PD];
__device__ float g_scale_atom[PD];
__device__ float g_shift_atom[PD];
__device__ float g_scale_cl[PD];
__device__ float g_shift_cl[PD];

// transposed + hi/lo-split weights, bf16:  [n][k] row-major per matrix
#define OFF_GA 0
#define OFF_GC 32768
#define OFF_SA 65536
#define OFF_SC 131072
#define OFF_MA 196608
#define OFF_MC 229376
__device__ __nv_bfloat16 g_Bt_hi[262144];
__device__ __nv_bfloat16 g_Bt_lo[262144];

// ---------------- helpers ---------------------------------------------------------
__device__ __forceinline__ uint32_t smem_u32(const void* p) {
    uint32_t a;
    asm("{ .reg .u64 t; cvta.to.shared.u64 t, %1; cvt.u32.u64 %0, t; }" : "=r"(a) : "l"(p));
    return a;
}
__device__ __forceinline__ void ldm_x4(uint32_t* r, uint32_t addr) {
    asm volatile("ldmatrix.sync.aligned.m8n8.x4.shared.b16 {%0,%1,%2,%3}, [%4];"
                 : "=r"(r[0]), "=r"(r[1]), "=r"(r[2]), "=r"(r[3]) : "r"(addr));
}
__device__ __forceinline__ void mma16816(float* c, const uint32_t* a, const uint32_t* b) {
    asm volatile("mma.sync.aligned.m16n8k16.row.col.f32.bf16.bf16.f32 "
                 "{%0,%1,%2,%3}, {%4,%5,%6,%7}, {%8,%9}, {%0,%1,%2,%3};"
                 : "+f"(c[0]), "+f"(c[1]), "+f"(c[2]), "+f"(c[3])
                 : "r"(a[0]), "r"(a[1]), "r"(a[2]), "r"(a[3]), "r"(b[0]), "r"(b[1]));
}

// ---------------- edge scatter kernels --------------------------------------------
__global__ void gine_scatter(const float* __restrict__ x, const float* __restrict__ ea,
                             const int* __restrict__ ei, int E, float* __restrict__ agg) {
    int warp = (blockIdx.x * blockDim.x + threadIdx.x) >> 5;
    int lane = threadIdx.x & 31;
    if (warp >= E) return;
    int src = ei[warp];
    int dst = ei[E + warp];
    float4 xv = reinterpret_cast<const float4*>(x + (size_t)src * HD)[lane];
    float4 ev = reinterpret_cast<const float4*>(ea + (size_t)warp * HD)[lane];
    float* a = agg + (size_t)dst * HD + lane * 4;
    atomicAdd(a + 0, fmaxf(xv.x + ev.x, 0.0f));
    atomicAdd(a + 1, fmaxf(xv.y + ev.y, 0.0f));
    atomicAdd(a + 2, fmaxf(xv.z + ev.z, 0.0f));
    atomicAdd(a + 3, fmaxf(xv.w + ev.w, 0.0f));
}

__global__ void sage_scatter(const float* __restrict__ xsrc, const int* __restrict__ ei,
                             int E, float* __restrict__ aggm, float* __restrict__ cnt) {
    int warp = (blockIdx.x * blockDim.x + threadIdx.x) >> 5;
    int lane = threadIdx.x & 31;
    if (warp >= E) return;
    int src = ei[warp];
    int dst = ei[E + warp];
    float4 xv = reinterpret_cast<const float4*>(xsrc + (size_t)src * HD)[lane];
    float* a = aggm + (size_t)dst * HD + lane * 4;
    atomicAdd(a + 0, xv.x);
    atomicAdd(a + 1, xv.y);
    atomicAdd(a + 2, xv.z);
    atomicAdd(a + 3, xv.w);
    if (lane == 0) atomicAdd(&cnt[dst], 1.0f);
}

// ---------------- BN stats --------------------------------------------------------
__global__ void colstats(const float* __restrict__ pre, int M, float* __restrict__ stats) {
    const int RPB = 256;
    int c = threadIdx.x;
    int r0 = blockIdx.x * RPB;
    int r1 = min(r0 + RPB, M);
    float s = 0.0f, ss = 0.0f;
    for (int r = r0; r < r1; r++) {
        float v = pre[(size_t)r * PD + c];
        s += v; ss += v * v;
    }
    atomicAdd(&stats[c], s);
    atomicAdd(&stats[PD + c], ss);
}

__global__ void bn_finalize(const float* __restrict__ stats, const float* __restrict__ gamma,
                            const float* __restrict__ beta, float invM,
                            float* __restrict__ scale, float* __restrict__ shift) {
    int c = threadIdx.x;
    float mu = stats[c] * invM;
    float var = stats[PD + c] * invM - mu * mu;
    float sc = gamma[c] * rsqrtf(var + BN_EPS);
    scale[c] = sc;
    shift[c] = beta[c] - mu * sc;
}

// ---------------- weight transpose + hi/lo split ----------------------------------
__global__ void wsplit(const float* __restrict__ W, int K, int N, int k_off, int K_out,
                       __nv_bfloat16* __restrict__ oh, __nv_bfloat16* __restrict__ ol) {
    int i = blockIdx.x * blockDim.x + threadIdx.x;
    if (i >= K * N) return;
    int k = i / N, n = i - k * N;
    float v = W[i];
    __nv_bfloat16 h = __float2bfloat16(v);
    float lo = v - __bfloat162float(h);
    oh[(size_t)n * K_out + k_off + k] = h;
    ol[(size_t)n * K_out + k_off + k] = __float2bfloat16(lo);
}

// ---------------- mma.sync split-bf16 GEMM with fused A-transforms ----------------
// C[M,*] tile = A[M,K] @ B[K,*]  (+bias); per-CTA tile 128x128; grid.y over N/128.
// mode 0 (GINE):  A = (1+eps)*A0 + A1                    (K=128)
// mode 1 (SAGE):  A = [A0/max(cnt,1) | A1]               (K=256)
// mode 2 (MERGE): A = relu(A0*scale+shift) + A1          (K=256)
// Bt_hi/lo: [n][K] row-major bf16 (pre-transposed, split).
// smem layout (bytes): bias @0 (512), AH @1024, AL @33792, BH @66560, BL @99328
#define SMO_BIAS 0
#define SMO_AH   1024
#define SMO_AL   33792
#define SMO_BH   66560
#define SMO_BL   99328
#define SMEM_TOT 132096

template <int K>
__global__ __launch_bounds__(256)
void hmma_gemm(int mode, int M,
               const float* __restrict__ A0, const float* __restrict__ A1,
               const float* __restrict__ aux0, const float* __restrict__ aux1,
               const __nv_bfloat16* __restrict__ Bt_hi,
               const __nv_bfloat16* __restrict__ Bt_lo,
               const float* __restrict__ bias0, const float* __restrict__ bias1,
               const float* __restrict__ epsPtr,
               float* __restrict__ C, int ldc) {
    extern __shared__ char smem[];
    uint32_t sb = smem_u32(smem);
    const int tid = threadIdx.x;
    const int wid = tid >> 5;
    const int lid = tid & 31;
    const int wm = wid & 3;          // warp m index (4): rows wm*32..+31
    const int wn = wid >> 2;         // warp n index (2): cols wn*64..+63
    const int m0 = blockIdx.x * 128;
    const int n0g = blockIdx.y * 128;

    // bias -> smem
    float* bias_s = reinterpret_cast<float*>(smem + SMO_BIAS);
    if (tid < 128) {
        float b = bias0[n0g + tid];
        if (bias1) b += bias1[n0g + tid];
        bias_s[tid] = b;
    }

    const float ef = (mode == 0) ? 1.0f + *epsPtr : 1.0f;

    float acc[2][8][4];
#pragma unroll
    for (int mt = 0; mt < 2; mt++)
#pragma unroll
        for (int nt = 0; nt < 8; nt++)
#pragma unroll
            for (int j = 0; j < 4; j++) acc[mt][nt][j] = 0.0f;

    for (int kk = 0; kk < K; kk += 128) {
        // ---- B tile: 128 n-rows x 128 k bf16 (hi & lo), 16B chunks, swizzled ----
#pragma unroll
        for (int it = 0; it < 8; it++) {
            int idx = tid + it * 256;          // 0..2047
            int n = idx >> 4;
            int ch = idx & 15;                 // k chunk (8 bf16 = 16B)
            const __nv_bfloat16* bh = Bt_hi + (size_t)(n0g + n) * K + kk + ch * 8;
            const __nv_bfloat16* bl = Bt_lo + (size_t)(n0g + n) * K + kk + ch * 8;
            uint4 h = *reinterpret_cast<const uint4*>(bh);
            uint4 l = *reinterpret_cast<const uint4*>(bl);
            uint32_t off = n * 256 + ((ch ^ (n & 7)) << 4);
            *reinterpret_cast<uint4*>(smem + SMO_BH + off) = h;
            *reinterpret_cast<uint4*>(smem + SMO_BL + off) = l;
        }
        // ---- A tile: 128 rows x 128 fp32 -> transform -> split -> bf16 ----
#pragma unroll
        for (int it = 0; it < 16; it++) {
            int idx = tid + it * 256;          // 0..4095 float4s
            int r = idx >> 5;
            int c4 = (idx & 31) * 4;
            int gr = m0 + r;
            int gk = kk + c4;
            float4 v = make_float4(0.f, 0.f, 0.f, 0.f);
            if (gr < M) {
                if (mode == 0) {
                    float4 a = *reinterpret_cast<const float4*>(A0 + (size_t)gr * 128 + gk);
                    float4 g = *reinterpret_cast<const float4*>(A1 + (size_t)gr * 128 + gk);
                    v.x = fmaf(ef, a.x, g.x); v.y = fmaf(ef, a.y, g.y);
                    v.z = fmaf(ef, a.z, g.z); v.w = fmaf(ef, a.w, g.w);
                } else if (mode == 1) {
                    if (gk < 128) {
                        float4 a = *reinterpret_cast<const float4*>(A0 + (size_t)gr * 128 + gk);
                        float inv = __frcp_rn(fmaxf(aux0[gr], 1.0f));
                        v.x = a.x * inv; v.y = a.y * inv; v.z = a.z * inv; v.w = a.w * inv;
                    } else {
                        v = *reinterpret_cast<const float4*>(A1 + (size_t)gr * 128 + (gk - 128));
                    }
                } else {
                    float4 p = *reinterpret_cast<const float4*>(A0 + (size_t)gr * 256 + gk);
                    float4 q = *reinterpret_cast<const float4*>(A1 + (size_t)gr * 256 + gk);
                    float4 s = *reinterpret_cast<const float4*>(aux0 + gk);
                    float4 hh = *reinterpret_cast<const float4*>(aux1 + gk);
                    v.x = fmaxf(fmaf(p.x, s.x, hh.x), 0.f) + q.x;
                    v.y = fmaxf(fmaf(p.y, s.y, hh.y), 0.f) + q.y;
                    v.z = fmaxf(fmaf(p.z, s.z, hh.z), 0.f) + q.z;
                    v.w = fmaxf(fmaf(p.w, s.w, hh.w), 0.f) + q.w;
                }
            }
            __nv_bfloat16 hx = __float2bfloat16(v.x), hy = __float2bfloat16(v.y);
            __nv_bfloat16 hz = __float2bfloat16(v.z), hw = __float2bfloat16(v.w);
            __nv_bfloat16 lx = __float2bfloat16(v.x - __bfloat162float(hx));
            __nv_bfloat16 ly = __float2bfloat16(v.y - __bfloat162float(hy));
            __nv_bfloat16 lz = __float2bfloat16(v.z - __bfloat162float(hz));
            __nv_bfloat16 lw = __float2bfloat16(v.w - __bfloat162float(hw));
            uint2 hp, lp;
            hp.x = (uint32_t)__bfloat16_as_ushort(hx) | ((uint32_t)__bfloat16_as_ushort(hy) << 16);
            hp.y = (uint32_t)__bfloat16_as_ushort(hz) | ((uint32_t)__bfloat16_as_ushort(hw) << 16);
            lp.x = (uint32_t)__bfloat16_as_ushort(lx) | ((uint32_t)__bfloat16_as_ushort(ly) << 16);
            lp.y = (uint32_t)__bfloat16_as_ushort(lz) | ((uint32_t)__bfloat16_as_ushort(lw) << 16);
            uint32_t off = r * 256 + (((c4 >> 3) ^ (r & 7)) << 4) + ((c4 & 4) << 1);
            *reinterpret_cast<uint2*>(smem + SMO_AH + off) = hp;
            *reinterpret_cast<uint2*>(smem + SMO_AL + off) = lp;
        }
        __syncthreads();

        // ---- compute: 8 k-steps of 16 ----
        const int arow = wm * 32 + (lid & 15);     // row for A ldmatrix (per m-tile +16)
        const int akp = lid >> 4;                  // 0/1 -> k chunk offset
        const int bn = wn * 64 + (lid & 7) + ((lid >> 4) << 3);  // per n-pair +16
        const int bkp = (lid >> 3) & 1;
#pragma unroll
        for (int ks = 0; ks < 8; ks++) {
            uint32_t ah[2][4], al[2][4];
#pragma unroll
            for (int mt = 0; mt < 2; mt++) {
                int r = arow + mt * 16;
                uint32_t ch = (uint32_t)((ks * 2 + akp) ^ (r & 7));
                uint32_t off = r * 256 + (ch << 4);
                ldm_x4(ah[mt], sb + SMO_AH + off);
                ldm_x4(al[mt], sb + SMO_AL + off);
            }
#pragma unroll
            for (int np = 0; np < 4; np++) {
                int n = bn + np * 16;
                uint32_t ch = (uint32_t)((ks * 2 + bkp) ^ (n & 7));
                uint32_t off = n * 256 + (ch << 4);
                uint32_t bh[4], bl[4];
                ldm_x4(bh, sb + SMO_BH + off);
                ldm_x4(bl, sb + SMO_BL + off);
#pragma unroll
                for (int mt = 0; mt < 2; mt++) {
#pragma unroll
                    for (int sn = 0; sn < 2; sn++) {
                        float* c = acc[mt][np * 2 + sn];
                        mma16816(c, ah[mt], bh + sn * 2);
                        mma16816(c, ah[mt], bl + sn * 2);
                        mma16816(c, al[mt], bh + sn * 2);
                    }
                }
            }
        }
        __syncthreads();
    }

    // ---- epilogue: write accumulators + bias ----
    const int g = lid >> 2;
    const int tig = lid & 3;
#pragma unroll
    for (int mt = 0; mt < 2; mt++) {
#pragma unroll
        for (int nt = 0; nt < 8; nt++) {
            int nl = wn * 64 + nt * 8 + 2 * tig;
            int n = n0g + nl;
            float b0 = bias_s[nl], b1 = bias_s[nl + 1];
            int m = m0 + wm * 32 + mt * 16 + g;
            if (m < M) {
                float2 o = make_float2(acc[mt][nt][0] + b0, acc[mt][nt][1] + b1);
                *reinterpret_cast<float2*>(C + (size_t)m * ldc + n) = o;
            }
            if (m + 8 < M) {
                float2 o = make_float2(acc[mt][nt][2] + b0, acc[mt][nt][3] + b1);
                *reinterpret_cast<float2*>(C + (size_t)(m + 8) * ldc + n) = o;
            }
        }
    }
}

// -----------------------------------------------------------------------------------
extern "C" void kernel_launch(void* const* d_in, const int* in_sizes, int n_in,
                              void* d_out, int out_size) {
    const float* x         = (const float*)d_in[0];
    const float* edge_attr = (const float*)d_in[1];
    const float* x_cl      = (const float*)d_in[2];
    const float* c2c_ea    = (const float*)d_in[3];

    int pbase, ebase;
    if (in_sizes[4] == 2 * EA) { ebase = 4; pbase = 8; }
    else                       { pbase = 4; ebase = 26; }

    const int* ei_a   = (const int*)d_in[ebase + 0];
    const int* ei_c2c = (const int*)d_in[ebase + 1];
    const int* ei_a2c = (const int*)d_in[ebase + 2];
    const int* ei_c2a = (const int*)d_in[ebase + 3];

    const float* atom_eps   = (const float*)d_in[pbase + 0];
    const float* atom_W     = (const float*)d_in[pbase + 1];
    const float* atom_b     = (const float*)d_in[pbase + 2];
    const float* atom_gamma = (const float*)d_in[pbase + 3];
    const float* atom_beta  = (const float*)d_in[pbase + 4];
    const float* cl_eps     = (const float*)d_in[pbase + 5];
    const float* cl_W       = (const float*)d_in[pbase + 6];
    const float* cl_b       = (const float*)d_in[pbase + 7];
    const float* cl_gamma   = (const float*)d_in[pbase + 8];
    const float* cl_beta    = (const float*)d_in[pbase + 9];
    const float* a2c_Wl     = (const float*)d_in[pbase + 10];
    const float* a2c_bl     = (const float*)d_in[pbase + 11];
    const float* a2c_Wr     = (const float*)d_in[pbase + 12];
    const float* a2c_br     = (const float*)d_in[pbase + 13];
    const float* c2a_Wl     = (const float*)d_in[pbase + 14];
    const float* c2a_bl     = (const float*)d_in[pbase + 15];
    const float* c2a_Wr     = (const float*)d_in[pbase + 16];
    const float* c2a_br     = (const float*)d_in[pbase + 17];
    const float* merge_atom_W = (const float*)d_in[pbase + 18];
    const float* merge_atom_b = (const float*)d_in[pbase + 19];
    const float* merge_cl_W   = (const float*)d_in[pbase + 20];
    const float* merge_cl_b   = (const float*)d_in[pbase + 21];

    float* out = (float*)d_out;

    float *p_agg_atom, *p_agg_cl, *p_aggm_c2a, *p_cnt_c2a, *p_aggm_a2c, *p_cnt_a2c;
    float *p_pre_atom, *p_pre_cl, *p_S_atom, *p_S_cl;
    float *p_stats_atom, *p_stats_cl, *p_scale_atom, *p_shift_atom, *p_scale_cl, *p_shift_cl;
    __nv_bfloat16 *p_Bt_hi, *p_Bt_lo;
    cudaGetSymbolAddress((void**)&p_agg_atom, g_agg_atom);
    cudaGetSymbolAddress((void**)&p_agg_cl, g_agg_cl);
    cudaGetSymbolAddress((void**)&p_aggm_c2a, g_aggm_c2a);
    cudaGetSymbolAddress((void**)&p_cnt_c2a, g_cnt_c2a);
    cudaGetSymbolAddress((void**)&p_aggm_a2c, g_aggm_a2c);
    cudaGetSymbolAddress((void**)&p_cnt_a2c, g_cnt_a2c);
    cudaGetSymbolAddress((void**)&p_pre_atom, g_pre_atom);
    cudaGetSymbolAddress((void**)&p_pre_cl, g_pre_cl);
    cudaGetSymbolAddress((void**)&p_S_atom, g_S_atom);
    cudaGetSymbolAddress((void**)&p_S_cl, g_S_cl);
    cudaGetSymbolAddress((void**)&p_stats_atom, g_stats_atom);
    cudaGetSymbolAddress((void**)&p_stats_cl, g_stats_cl);
    cudaGetSymbolAddress((void**)&p_scale_atom, g_scale_atom);
    cudaGetSymbolAddress((void**)&p_shift_atom, g_shift_atom);
    cudaGetSymbolAddress((void**)&p_scale_cl, g_scale_cl);
    cudaGetSymbolAddress((void**)&p_shift_cl, g_shift_cl);
    cudaGetSymbolAddress((void**)&p_Bt_hi, g_Bt_hi);
    cudaGetSymbolAddress((void**)&p_Bt_lo, g_Bt_lo);

    cudaMemsetAsync(p_agg_atom, 0, (size_t)NATOM * HD * 4, 0);
    cudaMemsetAsync(p_agg_cl, 0, (size_t)NCL * HD * 4, 0);
    cudaMemsetAsync(p_aggm_c2a, 0, (size_t)NATOM * HD * 4, 0);
    cudaMemsetAsync(p_cnt_c2a, 0, (size_t)NATOM * 4, 0);
    cudaMemsetAsync(p_aggm_a2c, 0, (size_t)NCL * HD * 4, 0);
    cudaMemsetAsync(p_cnt_a2c, 0, (size_t)NCL * 4, 0);
    cudaMemsetAsync(p_stats_atom, 0, 2 * PD * 4, 0);
    cudaMemsetAsync(p_stats_cl, 0, 2 * PD * 4, 0);

    cudaFuncSetAttribute((const void*)hmma_gemm<128>,
                         cudaFuncAttributeMaxDynamicSharedMemorySize, SMEM_TOT);
    cudaFuncSetAttribute((const void*)hmma_gemm<256>,
                         cudaFuncAttributeMaxDynamicSharedMemorySize, SMEM_TOT);

    // ---- weight transpose + split (tiny) ----
    {
        int t = 128 * 256;
        wsplit<<<(t + 255) / 256, 256>>>(atom_W, 128, 256, 0, 128, p_Bt_hi + OFF_GA, p_Bt_lo + OFF_GA);
        wsplit<<<(t + 255) / 256, 256>>>(cl_W, 128, 256, 0, 128, p_Bt_hi + OFF_GC, p_Bt_lo + OFF_GC);
        wsplit<<<(t + 255) / 256, 256>>>(c2a_Wl, 128, 256, 0, 256, p_Bt_hi + OFF_SA, p_Bt_lo + OFF_SA);
        wsplit<<<(t + 255) / 256, 256>>>(c2a_Wr, 128, 256, 128, 256, p_Bt_hi + OFF_SA, p_Bt_lo + OFF_SA);
        wsplit<<<(t + 255) / 256, 256>>>(a2c_Wl, 128, 256, 0, 256, p_Bt_hi + OFF_SC, p_Bt_lo + OFF_SC);
        wsplit<<<(t + 255) / 256, 256>>>(a2c_Wr, 128, 256, 128, 256, p_Bt_hi + OFF_SC, p_Bt_lo + OFF_SC);
        t = 256 * 128;
        wsplit<<<(t + 255) / 256, 256>>>(merge_atom_W, 256, 128, 0, 256, p_Bt_hi + OFF_MA, p_Bt_lo + OFF_MA);
        wsplit<<<(t + 255) / 256, 256>>>(merge_cl_W, 256, 128, 0, 256, p_Bt_hi + OFF_MC, p_Bt_lo + OFF_MC);
    }

    // ---- scatter passes ----
    gine_scatter<<<(EA * 32 + 255) / 256, 256>>>(x, edge_attr, ei_a, EA, p_agg_atom);
    gine_scatter<<<(EC * 32 + 255) / 256, 256>>>(x_cl, c2c_ea, ei_c2c, EC, p_agg_cl);
    sage_scatter<<<(EB * 32 + 255) / 256, 256>>>(x, ei_a2c, EB, p_aggm_a2c, p_cnt_a2c);
    sage_scatter<<<(EB * 32 + 255) / 256, 256>>>(x_cl, ei_c2a, EB, p_aggm_c2a, p_cnt_c2a);

    const int GA = (NATOM + 127) / 128;  // 782
    const int GC = (NCL + 127) / 128;    // 196

    // ---- GINE GEMMs (pre-BN): [M,128]@[128,256] ----
    hmma_gemm<128><<<dim3(GA, 2), 256, SMEM_TOT>>>(
        0, NATOM, x, p_agg_atom, nullptr, nullptr,
        p_Bt_hi + OFF_GA, p_Bt_lo + OFF_GA, atom_b, nullptr, atom_eps, p_pre_atom, 256);
    hmma_gemm<128><<<dim3(GC, 2), 256, SMEM_TOT>>>(
        0, NCL, x_cl, p_agg_cl, nullptr, nullptr,
        p_Bt_hi + OFF_GC, p_Bt_lo + OFF_GC, cl_b, nullptr, cl_eps, p_pre_cl, 256);

    // ---- BN stats ----
    colstats<<<(NATOM + 255) / 256, 256>>>(p_pre_atom, NATOM, p_stats_atom);
    colstats<<<(NCL + 255) / 256, 256>>>(p_pre_cl, NCL, p_stats_cl);
    bn_finalize<<<1, 256>>>(p_stats_atom, atom_gamma, atom_beta, 1.0f / NATOM,
                            p_scale_atom, p_shift_atom);
    bn_finalize<<<1, 256>>>(p_stats_cl, cl_gamma, cl_beta, 1.0f / NCL,
                            p_scale_cl, p_shift_cl);

    // ---- SAGE GEMMs: [mean | x_dst]@[Wl;Wr]+bl+br -> [M,256] ----
    hmma_gemm<256><<<dim3(GA, 2), 256, SMEM_TOT>>>(
        1, NATOM, p_aggm_c2a, x, p_cnt_c2a, nullptr,
        p_Bt_hi + OFF_SA, p_Bt_lo + OFF_SA, c2a_bl, c2a_br, nullptr, p_S_atom, 256);
    hmma_gemm<256><<<dim3(GC, 2), 256, SMEM_TOT>>>(
        1, NCL, p_aggm_a2c, x_cl, p_cnt_a2c, nullptr,
        p_Bt_hi + OFF_SC, p_Bt_lo + OFF_SC, a2c_bl, a2c_br, nullptr, p_S_cl, 256);

    // ---- merge GEMMs (fused BN+ReLU+residual) -> final output [M,128] ----
    hmma_gemm<256><<<dim3(GA, 1), 256, SMEM_TOT>>>(
        2, NATOM, p_pre_atom, p_S_atom, p_scale_atom, p_shift_atom,
        p_Bt_hi + OFF_MA, p_Bt_lo + OFF_MA, merge_atom_b, nullptr, nullptr, out, 128);
    hmma_gemm<256><<<dim3(GC, 1), 256, SMEM_TOT>>>(
        2, NCL, p_pre_cl, p_S_cl, p_scale_cl, p_shift_cl,
        p_Bt_hi + OFF_MC, p_Bt_lo + OFF_MC, merge_cl_b, nullptr, nullptr,
        out + (size_t)NATOM * HD, 128);
}

// round 6
// speedup vs baseline: 4.7127x; 1.3788x over previous
#include <cuda_runtime.h>
#include <cuda_bf16.h>
#include <cstdint>
#include <cstddef>

#define NATOM 100000
#define NCL   25000
#define EA    600000
#define EC    100000
#define EB    100000
#define HD    128
#define PD    256
#define BN_EPS 1e-5f

// ---------------- scratch (static device memory; no allocs allowed) ----------------
__device__ float g_agg_atom[(size_t)NATOM * HD];
__device__ float g_agg_cl[(size_t)NCL * HD];
__device__ float g_aggm_c2a[(size_t)NATOM * HD];
__device__ float g_cnt_c2a[NATOM];
__device__ float g_aggm_a2c[(size_t)NCL * HD];
__device__ float g_cnt_a2c[NCL];
__device__ float g_pre_atom[(size_t)NATOM * PD];
__device__ float g_pre_cl[(size_t)NCL * PD];
__device__ float g_S_atom[(size_t)NATOM * PD];
__device__ float g_S_cl[(size_t)NCL * PD];
__device__ float g_stats_atom[2 * PD];
__device__ float g_stats_cl[2 * PD];
__device__ float g_scale_atom[PD];
__device__ float g_shift_atom[PD];
__device__ float g_scale_cl[PD];
__device__ float g_shift_cl[PD];

// transposed + hi/lo-split weights, bf16:  [n][k] row-major per matrix
#define OFF_GA 0
#define OFF_GC 32768
#define OFF_SA 65536
#define OFF_SC 131072
#define OFF_MA 196608
#define OFF_MC 229376
__device__ __nv_bfloat16 g_Bt_hi[262144];
__device__ __nv_bfloat16 g_Bt_lo[262144];

// ---------------- helpers ---------------------------------------------------------
__device__ __forceinline__ uint32_t smem_u32(const void* p) {
    uint32_t a;
    asm("{ .reg .u64 t; cvta.to.shared.u64 t, %1; cvt.u32.u64 %0, t; }" : "=r"(a) : "l"(p));
    return a;
}
__device__ __forceinline__ void ldm_x4(uint32_t* r, uint32_t addr) {
    asm volatile("ldmatrix.sync.aligned.m8n8.x4.shared.b16 {%0,%1,%2,%3}, [%4];"
                 : "=r"(r[0]), "=r"(r[1]), "=r"(r[2]), "=r"(r[3]) : "r"(addr));
}
__device__ __forceinline__ void mma16816(float* c, const uint32_t* a, const uint32_t* b) {
    asm volatile("mma.sync.aligned.m16n8k16.row.col.f32.bf16.bf16.f32 "
                 "{%0,%1,%2,%3}, {%4,%5,%6,%7}, {%8,%9}, {%0,%1,%2,%3};"
                 : "+f"(c[0]), "+f"(c[1]), "+f"(c[2]), "+f"(c[3])
                 : "r"(a[0]), "r"(a[1]), "r"(a[2]), "r"(a[3]), "r"(b[0]), "r"(b[1]));
}
__device__ __forceinline__ void red_v4(float* p, float a, float b, float c, float d) {
    asm volatile("red.global.add.v4.f32 [%0], {%1,%2,%3,%4};"
                 :: "l"(p), "f"(a), "f"(b), "f"(c), "f"(d) : "memory");
}

// ---------------- edge scatter kernels (v4 reductions) ----------------------------
__global__ void gine_scatter(const float* __restrict__ x, const float* __restrict__ ea,
                             const int* __restrict__ ei, int E, float* __restrict__ agg) {
    int warp = (blockIdx.x * blockDim.x + threadIdx.x) >> 5;
    int lane = threadIdx.x & 31;
    if (warp >= E) return;
    int src = ei[warp];
    int dst = ei[E + warp];
    float4 xv = reinterpret_cast<const float4*>(x + (size_t)src * HD)[lane];
    float4 ev = reinterpret_cast<const float4*>(ea + (size_t)warp * HD)[lane];
    red_v4(agg + (size_t)dst * HD + lane * 4,
           fmaxf(xv.x + ev.x, 0.0f), fmaxf(xv.y + ev.y, 0.0f),
           fmaxf(xv.z + ev.z, 0.0f), fmaxf(xv.w + ev.w, 0.0f));
}

__global__ void sage_scatter(const float* __restrict__ xsrc, const int* __restrict__ ei,
                             int E, float* __restrict__ aggm, float* __restrict__ cnt) {
    int warp = (blockIdx.x * blockDim.x + threadIdx.x) >> 5;
    int lane = threadIdx.x & 31;
    if (warp >= E) return;
    int src = ei[warp];
    int dst = ei[E + warp];
    float4 xv = reinterpret_cast<const float4*>(xsrc + (size_t)src * HD)[lane];
    red_v4(aggm + (size_t)dst * HD + lane * 4, xv.x, xv.y, xv.z, xv.w);
    if (lane == 0) atomicAdd(&cnt[dst], 1.0f);
}

// ---------------- BN stats --------------------------------------------------------
__global__ void colstats(const float* __restrict__ pre, int M, float* __restrict__ stats) {
    const int RPB = 256;
    int c = threadIdx.x;
    int r0 = blockIdx.x * RPB;
    int r1 = min(r0 + RPB, M);
    float s = 0.0f, ss = 0.0f;
    for (int r = r0; r < r1; r++) {
        float v = pre[(size_t)r * PD + c];
        s += v; ss += v * v;
    }
    atomicAdd(&stats[c], s);
    atomicAdd(&stats[PD + c], ss);
}

__global__ void bn_finalize(const float* __restrict__ stats, const float* __restrict__ gamma,
                            const float* __restrict__ beta, float invM,
                            float* __restrict__ scale, float* __restrict__ shift) {
    int c = threadIdx.x;
    float mu = stats[c] * invM;
    float var = stats[PD + c] * invM - mu * mu;
    float sc = gamma[c] * rsqrtf(var + BN_EPS);
    scale[c] = sc;
    shift[c] = beta[c] - mu * sc;
}

// ---------------- fused weight transpose + hi/lo split (one launch) ---------------
struct WsplitArgs { const float* src[8]; };
__constant__ int c_ws_N[8]     = {256, 256, 256, 256, 256, 256, 128, 128};
__constant__ int c_ws_koff[8]  = {0, 0, 0, 128, 0, 128, 0, 0};
__constant__ int c_ws_kout[8]  = {128, 128, 256, 256, 256, 256, 256, 256};
__constant__ int c_ws_doff[8]  = {OFF_GA, OFF_GC, OFF_SA, OFF_SA, OFF_SC, OFF_SC, OFF_MA, OFF_MC};

__global__ void wsplit_all(WsplitArgs args,
                           __nv_bfloat16* __restrict__ oh, __nv_bfloat16* __restrict__ ol) {
    int i = blockIdx.x * blockDim.x + threadIdx.x;   // 0 .. 262143
    int seg = i >> 15;
    int w = i & 32767;
    int N = c_ws_N[seg];
    int k = w / N, n = w - k * N;
    float v = args.src[seg][w];
    __nv_bfloat16 h = __float2bfloat16(v);
    float lo = v - __bfloat162float(h);
    size_t o = (size_t)n * c_ws_kout[seg] + c_ws_koff[seg] + k + c_ws_doff[seg];
    oh[o] = h;
    ol[o] = __float2bfloat16(lo);
}

// ---------------- mma.sync split-bf16 GEMM with fused A-transforms ----------------
// per-CTA tile: 128 rows x NTILE cols; BLOCK = 2*NTILE threads.
// mode 0 (GINE):  A = (1+eps)*A0 + A1                    (K=128)
// mode 1 (SAGE):  A = [A0/max(cnt,1) | A1]               (K=256)
// mode 2 (MERGE): A = relu(A0*scale+shift) + A1          (K=256)
// smem (bytes): bias @0 (1024), AH @1024, AL @33792, BH @66560, BL @66560+NTILE*256
#define SMO_AH   1024
#define SMO_AL   33792
#define SMO_BH   66560

template <int K, int NTILE>
__global__ __launch_bounds__(NTILE * 2)
void hmma_gemm(int mode, int M,
               const float* __restrict__ A0, const float* __restrict__ A1,
               const float* __restrict__ aux0, const float* __restrict__ aux1,
               const __nv_bfloat16* __restrict__ Bt_hi,
               const __nv_bfloat16* __restrict__ Bt_lo,
               const float* __restrict__ bias0, const float* __restrict__ bias1,
               const float* __restrict__ epsPtr,
               float* __restrict__ C, int ldc) {
    constexpr int BLOCK = NTILE * 2;
    constexpr int SMO_BL = SMO_BH + NTILE * 256;
    extern __shared__ char smem[];
    uint32_t sb = smem_u32(smem);
    const int tid = threadIdx.x;
    const int wid = tid >> 5;
    const int lid = tid & 31;
    const int wm = wid & 3;          // warp m index (4): rows wm*32..+31
    const int wn = wid >> 2;         // warp n index: cols wn*64..+63
    const int m0 = blockIdx.x * 128;

    float* bias_s = reinterpret_cast<float*>(smem);
    if (tid < NTILE) {
        float b = bias0[tid];
        if (bias1) b += bias1[tid];
        bias_s[tid] = b;
    }

    const float ef = (mode == 0) ? 1.0f + *epsPtr : 1.0f;

    float acc[2][8][4];
#pragma unroll
    for (int mt = 0; mt < 2; mt++)
#pragma unroll
        for (int nt = 0; nt < 8; nt++)
#pragma unroll
            for (int j = 0; j < 4; j++) acc[mt][nt][j] = 0.0f;

    for (int kk = 0; kk < K; kk += 128) {
        // ---- B tile: NTILE n-rows x 128 k bf16 (hi & lo), 16B chunks, swizzled ----
#pragma unroll
        for (int it = 0; it < 8; it++) {
            int idx = tid + it * BLOCK;        // 0..NTILE*16-1
            int n = idx >> 4;
            int ch = idx & 15;
            const __nv_bfloat16* bh = Bt_hi + (size_t)n * K + kk + ch * 8;
            const __nv_bfloat16* bl = Bt_lo + (size_t)n * K + kk + ch * 8;
            uint4 h = *reinterpret_cast<const uint4*>(bh);
            uint4 l = *reinterpret_cast<const uint4*>(bl);
            uint32_t off = n * 256 + ((ch ^ (n & 7)) << 4);
            *reinterpret_cast<uint4*>(smem + SMO_BH + off) = h;
            *reinterpret_cast<uint4*>(smem + SMO_BL + off) = l;
        }
        // ---- A tile: 128 rows x 128 fp32 -> transform -> split -> bf16 ----
#pragma unroll
        for (int it = 0; it < 4096 / BLOCK; it++) {
            int idx = tid + it * BLOCK;        // 0..4095 float4s
            int r = idx >> 5;
            int c4 = (idx & 31) * 4;
            int gr = m0 + r;
            int gk = kk + c4;
            float4 v = make_float4(0.f, 0.f, 0.f, 0.f);
            if (gr < M) {
                if (mode == 0) {
                    float4 a = *reinterpret_cast<const float4*>(A0 + (size_t)gr * 128 + gk);
                    float4 g = *reinterpret_cast<const float4*>(A1 + (size_t)gr * 128 + gk);
                    v.x = fmaf(ef, a.x, g.x); v.y = fmaf(ef, a.y, g.y);
                    v.z = fmaf(ef, a.z, g.z); v.w = fmaf(ef, a.w, g.w);
                } else if (mode == 1) {
                    if (gk < 128) {
                        float4 a = *reinterpret_cast<const float4*>(A0 + (size_t)gr * 128 + gk);
                        float inv = __frcp_rn(fmaxf(aux0[gr], 1.0f));
                        v.x = a.x * inv; v.y = a.y * inv; v.z = a.z * inv; v.w = a.w * inv;
                    } else {
                        v = *reinterpret_cast<const float4*>(A1 + (size_t)gr * 128 + (gk - 128));
                    }
                } else {
                    float4 p = *reinterpret_cast<const float4*>(A0 + (size_t)gr * 256 + gk);
                    float4 q = *reinterpret_cast<const float4*>(A1 + (size_t)gr * 256 + gk);
                    float4 s = *reinterpret_cast<const float4*>(aux0 + gk);
                    float4 hh = *reinterpret_cast<const float4*>(aux1 + gk);
                    v.x = fmaxf(fmaf(p.x, s.x, hh.x), 0.f) + q.x;
                    v.y = fmaxf(fmaf(p.y, s.y, hh.y), 0.f) + q.y;
                    v.z = fmaxf(fmaf(p.z, s.z, hh.z), 0.f) + q.z;
                    v.w = fmaxf(fmaf(p.w, s.w, hh.w), 0.f) + q.w;
                }
            }
            __nv_bfloat16 hx = __float2bfloat16(v.x), hy = __float2bfloat16(v.y);
            __nv_bfloat16 hz = __float2bfloat16(v.z), hw = __float2bfloat16(v.w);
            __nv_bfloat16 lx = __float2bfloat16(v.x - __bfloat162float(hx));
            __nv_bfloat16 ly = __float2bfloat16(v.y - __bfloat162float(hy));
            __nv_bfloat16 lz = __float2bfloat16(v.z - __bfloat162float(hz));
            __nv_bfloat16 lw = __float2bfloat16(v.w - __bfloat162float(hw));
            uint2 hp, lp;
            hp.x = (uint32_t)__bfloat16_as_ushort(hx) | ((uint32_t)__bfloat16_as_ushort(hy) << 16);
            hp.y = (uint32_t)__bfloat16_as_ushort(hz) | ((uint32_t)__bfloat16_as_ushort(hw) << 16);
            lp.x = (uint32_t)__bfloat16_as_ushort(lx) | ((uint32_t)__bfloat16_as_ushort(ly) << 16);
            lp.y = (uint32_t)__bfloat16_as_ushort(lz) | ((uint32_t)__bfloat16_as_ushort(lw) << 16);
            uint32_t off = r * 256 + (((c4 >> 3) ^ (r & 7)) << 4) + ((c4 & 4) << 1);
            *reinterpret_cast<uint2*>(smem + SMO_AH + off) = hp;
            *reinterpret_cast<uint2*>(smem + SMO_AL + off) = lp;
        }
        __syncthreads();

        // ---- compute: 8 k-steps of 16 ----
        const int arow = wm * 32 + (lid & 15);
        const int akp = lid >> 4;
        const int bn = wn * 64 + (lid & 7) + ((lid >> 4) << 3);
        const int bkp = (lid >> 3) & 1;
#pragma unroll
        for (int ks = 0; ks < 8; ks++) {
            uint32_t ah[2][4], al[2][4];
#pragma unroll
            for (int mt = 0; mt < 2; mt++) {
                int r = arow + mt * 16;
                uint32_t ch = (uint32_t)((ks * 2 + akp) ^ (r & 7));
                uint32_t off = r * 256 + (ch << 4);
                ldm_x4(ah[mt], sb + SMO_AH + off);
                ldm_x4(al[mt], sb + SMO_AL + off);
            }
#pragma unroll
            for (int np = 0; np < 4; np++) {
                int n = bn + np * 16;
                uint32_t ch = (uint32_t)((ks * 2 + bkp) ^ (n & 7));
                uint32_t off = n * 256 + (ch << 4);
                uint32_t bh[4], bl[4];
                ldm_x4(bh, sb + SMO_BH + off);
                ldm_x4(bl, sb + SMO_BL + off);
#pragma unroll
                for (int mt = 0; mt < 2; mt++) {
#pragma unroll
                    for (int sn = 0; sn < 2; sn++) {
                        float* c = acc[mt][np * 2 + sn];
                        mma16816(c, ah[mt], bh + sn * 2);
                        mma16816(c, ah[mt], bl + sn * 2);
                        mma16816(c, al[mt], bh + sn * 2);
                    }
                }
            }
        }
        __syncthreads();
    }

    // ---- epilogue ----
    const int g = lid >> 2;
    const int tig = lid & 3;
#pragma unroll
    for (int mt = 0; mt < 2; mt++) {
#pragma unroll
        for (int nt = 0; nt < 8; nt++) {
            int nl = wn * 64 + nt * 8 + 2 * tig;
            float b0 = bias_s[nl], b1 = bias_s[nl + 1];
            int m = m0 + wm * 32 + mt * 16 + g;
            if (m < M) {
                float2 o = make_float2(acc[mt][nt][0] + b0, acc[mt][nt][1] + b1);
                *reinterpret_cast<float2*>(C + (size_t)m * ldc + nl) = o;
            }
            if (m + 8 < M) {
                float2 o = make_float2(acc[mt][nt][2] + b0, acc[mt][nt][3] + b1);
                *reinterpret_cast<float2*>(C + (size_t)(m + 8) * ldc + nl) = o;
            }
        }
    }
}

// -----------------------------------------------------------------------------------
extern "C" void kernel_launch(void* const* d_in, const int* in_sizes, int n_in,
                              void* d_out, int out_size) {
    const float* x         = (const float*)d_in[0];
    const float* edge_attr = (const float*)d_in[1];
    const float* x_cl      = (const float*)d_in[2];
    const float* c2c_ea    = (const float*)d_in[3];

    int pbase, ebase;
    if (in_sizes[4] == 2 * EA) { ebase = 4; pbase = 8; }
    else                       { pbase = 4; ebase = 26; }

    const int* ei_a   = (const int*)d_in[ebase + 0];
    const int* ei_c2c = (const int*)d_in[ebase + 1];
    const int* ei_a2c = (const int*)d_in[ebase + 2];
    const int* ei_c2a = (const int*)d_in[ebase + 3];

    const float* atom_eps   = (const float*)d_in[pbase + 0];
    const float* atom_W     = (const float*)d_in[pbase + 1];
    const float* atom_b     = (const float*)d_in[pbase + 2];
    const float* atom_gamma = (const float*)d_in[pbase + 3];
    const float* atom_beta  = (const float*)d_in[pbase + 4];
    const float* cl_eps     = (const float*)d_in[pbase + 5];
    const float* cl_W       = (const float*)d_in[pbase + 6];
    const float* cl_b       = (const float*)d_in[pbase + 7];
    const float* cl_gamma   = (const float*)d_in[pbase + 8];
    const float* cl_beta    = (const float*)d_in[pbase + 9];
    const float* a2c_Wl     = (const float*)d_in[pbase + 10];
    const float* a2c_bl     = (const float*)d_in[pbase + 11];
    const float* a2c_Wr     = (const float*)d_in[pbase + 12];
    const float* a2c_br     = (const float*)d_in[pbase + 13];
    const float* c2a_Wl     = (const float*)d_in[pbase + 14];
    const float* c2a_bl     = (const float*)d_in[pbase + 15];
    const float* c2a_Wr     = (const float*)d_in[pbase + 16];
    const float* c2a_br     = (const float*)d_in[pbase + 17];
    const float* merge_atom_W = (const float*)d_in[pbase + 18];
    const float* merge_atom_b = (const float*)d_in[pbase + 19];
    const float* merge_cl_W   = (const float*)d_in[pbase + 20];
    const float* merge_cl_b   = (const float*)d_in[pbase + 21];

    float* out = (float*)d_out;

    float *p_agg_atom, *p_agg_cl, *p_aggm_c2a, *p_cnt_c2a, *p_aggm_a2c, *p_cnt_a2c;
    float *p_pre_atom, *p_pre_cl, *p_S_atom, *p_S_cl;
    float *p_stats_atom, *p_stats_cl, *p_scale_atom, *p_shift_atom, *p_scale_cl, *p_shift_cl;
    __nv_bfloat16 *p_Bt_hi, *p_Bt_lo;
    cudaGetSymbolAddress((void**)&p_agg_atom, g_agg_atom);
    cudaGetSymbolAddress((void**)&p_agg_cl, g_agg_cl);
    cudaGetSymbolAddress((void**)&p_aggm_c2a, g_aggm_c2a);
    cudaGetSymbolAddress((void**)&p_cnt_c2a, g_cnt_c2a);
    cudaGetSymbolAddress((void**)&p_aggm_a2c, g_aggm_a2c);
    cudaGetSymbolAddress((void**)&p_cnt_a2c, g_cnt_a2c);
    cudaGetSymbolAddress((void**)&p_pre_atom, g_pre_atom);
    cudaGetSymbolAddress((void**)&p_pre_cl, g_pre_cl);
    cudaGetSymbolAddress((void**)&p_S_atom, g_S_atom);
    cudaGetSymbolAddress((void**)&p_S_cl, g_S_cl);
    cudaGetSymbolAddress((void**)&p_stats_atom, g_stats_atom);
    cudaGetSymbolAddress((void**)&p_stats_cl, g_stats_cl);
    cudaGetSymbolAddress((void**)&p_scale_atom, g_scale_atom);
    cudaGetSymbolAddress((void**)&p_shift_atom, g_shift_atom);
    cudaGetSymbolAddress((void**)&p_scale_cl, g_scale_cl);
    cudaGetSymbolAddress((void**)&p_shift_cl, g_shift_cl);
    cudaGetSymbolAddress((void**)&p_Bt_hi, g_Bt_hi);
    cudaGetSymbolAddress((void**)&p_Bt_lo, g_Bt_lo);

    cudaMemsetAsync(p_agg_atom, 0, (size_t)NATOM * HD * 4, 0);
    cudaMemsetAsync(p_agg_cl, 0, (size_t)NCL * HD * 4, 0);
    cudaMemsetAsync(p_aggm_c2a, 0, (size_t)NATOM * HD * 4, 0);
    cudaMemsetAsync(p_cnt_c2a, 0, (size_t)NATOM * 4, 0);
    cudaMemsetAsync(p_aggm_a2c, 0, (size_t)NCL * HD * 4, 0);
    cudaMemsetAsync(p_cnt_a2c, 0, (size_t)NCL * 4, 0);
    cudaMemsetAsync(p_stats_atom, 0, 2 * PD * 4, 0);
    cudaMemsetAsync(p_stats_cl, 0, 2 * PD * 4, 0);

    const int SMEM_256 = 66560 + 256 * 256 * 2;  // 197632
    const int SMEM_128 = 66560 + 128 * 256 * 2;  // 132096
    cudaFuncSetAttribute((const void*)hmma_gemm<128, 256>,
                         cudaFuncAttributeMaxDynamicSharedMemorySize, SMEM_256);
    cudaFuncSetAttribute((const void*)hmma_gemm<256, 256>,
                         cudaFuncAttributeMaxDynamicSharedMemorySize, SMEM_256);
    cudaFuncSetAttribute((const void*)hmma_gemm<256, 128>,
                         cudaFuncAttributeMaxDynamicSharedMemorySize, SMEM_128);

    // ---- fused weight transpose + split (one launch) ----
    {
        WsplitArgs wa;
        wa.src[0] = atom_W;  wa.src[1] = cl_W;
        wa.src[2] = c2a_Wl;  wa.src[3] = c2a_Wr;
        wa.src[4] = a2c_Wl;  wa.src[5] = a2c_Wr;
        wa.src[6] = merge_atom_W; wa.src[7] = merge_cl_W;
        wsplit_all<<<1024, 256>>>(wa, p_Bt_hi, p_Bt_lo);
    }

    // ---- scatter passes ----
    gine_scatter<<<(EA * 32 + 255) / 256, 256>>>(x, edge_attr, ei_a, EA, p_agg_atom);
    gine_scatter<<<(EC * 32 + 255) / 256, 256>>>(x_cl, c2c_ea, ei_c2c, EC, p_agg_cl);
    sage_scatter<<<(EB * 32 + 255) / 256, 256>>>(x, ei_a2c, EB, p_aggm_a2c, p_cnt_a2c);
    sage_scatter<<<(EB * 32 + 255) / 256, 256>>>(x_cl, ei_c2a, EB, p_aggm_c2a, p_cnt_c2a);

    const int GA = (NATOM + 127) / 128;  // 782
    const int GC = (NCL + 127) / 128;    // 196

    // ---- GINE GEMMs (pre-BN): [M,128]@[128,256], full N in one CTA ----
    hmma_gemm<128, 256><<<GA, 512, SMEM_256>>>(
        0, NATOM, x, p_agg_atom, nullptr, nullptr,
        p_Bt_hi + OFF_GA, p_Bt_lo + OFF_GA, atom_b, nullptr, atom_eps, p_pre_atom, 256);
    hmma_gemm<128, 256><<<GC, 512, SMEM_256>>>(
        0, NCL, x_cl, p_agg_cl, nullptr, nullptr,
        p_Bt_hi + OFF_GC, p_Bt_lo + OFF_GC, cl_b, nullptr, cl_eps, p_pre_cl, 256);

    // ---- BN stats ----
    colstats<<<(NATOM + 255) / 256, 256>>>(p_pre_atom, NATOM, p_stats_atom);
    colstats<<<(NCL + 255) / 256, 256>>>(p_pre_cl, NCL, p_stats_cl);
    bn_finalize<<<1, 256>>>(p_stats_atom, atom_gamma, atom_beta, 1.0f / NATOM,
                            p_scale_atom, p_shift_atom);
    bn_finalize<<<1, 256>>>(p_stats_cl, cl_gamma, cl_beta, 1.0f / NCL,
                            p_scale_cl, p_shift_cl);

    // ---- SAGE GEMMs: [mean | x_dst]@[Wl;Wr]+bl+br -> [M,256] ----
    hmma_gemm<256, 256><<<GA, 512, SMEM_256>>>(
        1, NATOM, p_aggm_c2a, x, p_cnt_c2a, nullptr,
        p_Bt_hi + OFF_SA, p_Bt_lo + OFF_SA, c2a_bl, c2a_br, nullptr, p_S_atom, 256);
    hmma_gemm<256, 256><<<GC, 512, SMEM_256>>>(
        1, NCL, p_aggm_a2c, x_cl, p_cnt_a2c, nullptr,
        p_Bt_hi + OFF_SC, p_Bt_lo + OFF_SC, a2c_bl, a2c_br, nullptr, p_S_cl, 256);

    // ---- merge GEMMs (fused BN+ReLU+residual) -> final output [M,128] ----
    hmma_gemm<256, 128><<<GA, 256, SMEM_128>>>(
        2, NATOM, p_pre_atom, p_S_atom, p_scale_atom, p_shift_atom,
        p_Bt_hi + OFF_MA, p_Bt_lo + OFF_MA, merge_atom_b, nullptr, nullptr, out, 128);
    hmma_gemm<256, 128><<<GC, 256, SMEM_128>>>(
        2, NCL, p_pre_cl, p_S_cl, p_scale_cl, p_shift_cl,
        p_Bt_hi + OFF_MC, p_Bt_lo + OFF_MC, merge_cl_b, nullptr, nullptr,
        out + (size_t)NATOM * HD, 128);
}

// round 7
// speedup vs baseline: 5.1311x; 1.0888x over previous
#include <cuda_runtime.h>
#include <cuda_bf16.h>
#include <cstdint>
#include <cstddef>

#define NATOM 100000
#define NCL   25000
#define EA    600000
#define EC    100000
#define EB    100000
#define HD    128
#define PD    256
#define BN_EPS 1e-5f

// ---------------- scratch (static device memory; no allocs allowed) ----------------
__device__ float g_agg_atom[(size_t)NATOM * HD];
__device__ float g_agg_cl[(size_t)NCL * HD];
__device__ float g_aggm_c2a[(size_t)NATOM * HD];
__device__ float g_cnt_c2a[NATOM];
__device__ float g_aggm_a2c[(size_t)NCL * HD];
__device__ float g_cnt_a2c[NCL];
__device__ float g_pre_atom[(size_t)NATOM * PD];
__device__ float g_pre_cl[(size_t)NCL * PD];
__device__ float g_S_atom[(size_t)NATOM * PD];
__device__ float g_S_cl[(size_t)NCL * PD];
__device__ float g_stats_atom[2 * PD];
__device__ float g_stats_cl[2 * PD];
__device__ float g_scale_atom[PD];
__device__ float g_shift_atom[PD];
__device__ float g_scale_cl[PD];
__device__ float g_shift_cl[PD];

// transposed + hi/lo-split weights, bf16:  [n][k] row-major per matrix
#define OFF_GA 0
#define OFF_GC 32768
#define OFF_SA 65536
#define OFF_SC 131072
#define OFF_MA 196608
#define OFF_MC 229376
__device__ __nv_bfloat16 g_Bt_hi[262144];
__device__ __nv_bfloat16 g_Bt_lo[262144];

// ---------------- helpers ---------------------------------------------------------
__device__ __forceinline__ uint32_t smem_u32(const void* p) {
    uint32_t a;
    asm("{ .reg .u64 t; cvta.to.shared.u64 t, %1; cvt.u32.u64 %0, t; }" : "=r"(a) : "l"(p));
    return a;
}
__device__ __forceinline__ void ldm_x4(uint32_t* r, uint32_t addr) {
    asm volatile("ldmatrix.sync.aligned.m8n8.x4.shared.b16 {%0,%1,%2,%3}, [%4];"
                 : "=r"(r[0]), "=r"(r[1]), "=r"(r[2]), "=r"(r[3]) : "r"(addr));
}
__device__ __forceinline__ void mma16816(float* c, const uint32_t* a, const uint32_t* b) {
    asm volatile("mma.sync.aligned.m16n8k16.row.col.f32.bf16.bf16.f32 "
                 "{%0,%1,%2,%3}, {%4,%5,%6,%7}, {%8,%9}, {%0,%1,%2,%3};"
                 : "+f"(c[0]), "+f"(c[1]), "+f"(c[2]), "+f"(c[3])
                 : "r"(a[0]), "r"(a[1]), "r"(a[2]), "r"(a[3]), "r"(b[0]), "r"(b[1]));
}
__device__ __forceinline__ void red_v4(float* p, float a, float b, float c, float d) {
    asm volatile("red.global.add.v4.f32 [%0], {%1,%2,%3,%4};"
                 :: "l"(p), "f"(a), "f"(b), "f"(c), "f"(d) : "memory");
}
__device__ __forceinline__ void cp16(uint32_t s, const void* g) {
    asm volatile("cp.async.cg.shared.global [%0], [%1], 16;" :: "r"(s), "l"(g));
}
__device__ __forceinline__ uint32_t pack_lo_bf16(float lox, float loy) {
    uint32_t r;
    asm("cvt.rn.bf16x2.f32 %0, %1, %2;" : "=r"(r) : "f"(loy), "f"(lox));
    return r;
}

// ---------------- edge scatter kernels (v4 reductions) ----------------------------
__global__ void gine_scatter(const float* __restrict__ x, const float* __restrict__ ea,
                             const int* __restrict__ ei, int E, float* __restrict__ agg) {
    int warp = (blockIdx.x * blockDim.x + threadIdx.x) >> 5;
    int lane = threadIdx.x & 31;
    if (warp >= E) return;
    int src = ei[warp];
    int dst = ei[E + warp];
    float4 xv = reinterpret_cast<const float4*>(x + (size_t)src * HD)[lane];
    float4 ev = reinterpret_cast<const float4*>(ea + (size_t)warp * HD)[lane];
    red_v4(agg + (size_t)dst * HD + lane * 4,
           fmaxf(xv.x + ev.x, 0.0f), fmaxf(xv.y + ev.y, 0.0f),
           fmaxf(xv.z + ev.z, 0.0f), fmaxf(xv.w + ev.w, 0.0f));
}

__global__ void sage_scatter(const float* __restrict__ xsrc, const int* __restrict__ ei,
                             int E, float* __restrict__ aggm, float* __restrict__ cnt) {
    int warp = (blockIdx.x * blockDim.x + threadIdx.x) >> 5;
    int lane = threadIdx.x & 31;
    if (warp >= E) return;
    int src = ei[warp];
    int dst = ei[E + warp];
    float4 xv = reinterpret_cast<const float4*>(xsrc + (size_t)src * HD)[lane];
    red_v4(aggm + (size_t)dst * HD + lane * 4, xv.x, xv.y, xv.z, xv.w);
    if (lane == 0) atomicAdd(&cnt[dst], 1.0f);
}

// ---------------- BN finalize -----------------------------------------------------
__global__ void bn_finalize(const float* __restrict__ stats, const float* __restrict__ gamma,
                            const float* __restrict__ beta, float invM,
                            float* __restrict__ scale, float* __restrict__ shift) {
    int c = threadIdx.x;
    float mu = stats[c] * invM;
    float var = stats[PD + c] * invM - mu * mu;
    float sc = gamma[c] * rsqrtf(var + BN_EPS);
    scale[c] = sc;
    shift[c] = beta[c] - mu * sc;
}

// ---------------- fused weight transpose + hi/lo split (one launch) ---------------
struct WsplitArgs { const float* src[8]; };
__constant__ int c_ws_N[8]     = {256, 256, 256, 256, 256, 256, 128, 128};
__constant__ int c_ws_koff[8]  = {0, 0, 0, 128, 0, 128, 0, 0};
__constant__ int c_ws_kout[8]  = {128, 128, 256, 256, 256, 256, 256, 256};
__constant__ int c_ws_doff[8]  = {OFF_GA, OFF_GC, OFF_SA, OFF_SA, OFF_SC, OFF_SC, OFF_MA, OFF_MC};

__global__ void wsplit_all(WsplitArgs args,
                           __nv_bfloat16* __restrict__ oh, __nv_bfloat16* __restrict__ ol) {
    int i = blockIdx.x * blockDim.x + threadIdx.x;   // 0 .. 262143
    int seg = i >> 15;
    int w = i & 32767;
    int N = c_ws_N[seg];
    int k = w / N, n = w - k * N;
    float v = args.src[seg][w];
    uint32_t bits = __float_as_uint(v);
    uint32_t hbits = bits & 0xFFFF0000u;
    float lo = v - __uint_as_float(hbits);
    size_t o = (size_t)n * c_ws_kout[seg] + c_ws_koff[seg] + k + c_ws_doff[seg];
    oh[o] = __ushort_as_bfloat16((unsigned short)(hbits >> 16));
    ol[o] = __float2bfloat16(lo);
}

// ---------------- mma.sync split-bf16 GEMM with fused A-transforms ----------------
// per-CTA tile: 128 rows x NTILE cols; BLOCK = 2*NTILE threads.
// mode 0 (GINE):  A = (1+eps)*A0 + A1                    (K=128)  [+ fused col stats]
// mode 1 (SAGE):  A = [A0/max(cnt,1) | A1]               (K=256)
// mode 2 (MERGE): A = relu(A0*scale+shift) + A1          (K=256)
#define SMO_AH   1024
#define SMO_AL   33792
#define SMO_BH   66560

template <int K, int NTILE>
__global__ __launch_bounds__(NTILE * 2)
void hmma_gemm(int mode, int M,
               const float* __restrict__ A0, const float* __restrict__ A1,
               const float* __restrict__ aux0, const float* __restrict__ aux1,
               const __nv_bfloat16* __restrict__ Bt_hi,
               const __nv_bfloat16* __restrict__ Bt_lo,
               const float* __restrict__ bias0, const float* __restrict__ bias1,
               const float* __restrict__ epsPtr, float* __restrict__ statsG,
               float* __restrict__ C, int ldc) {
    constexpr int BLOCK = NTILE * 2;
    constexpr int SMO_BL = SMO_BH + NTILE * 256;
    extern __shared__ char smem[];
    uint32_t sb = smem_u32(smem);
    const int tid = threadIdx.x;
    const int wid = tid >> 5;
    const int lid = tid & 31;
    const int wm = wid & 3;          // warp m index (4): rows wm*32..+31
    const int wn = wid >> 2;         // warp n index: cols wn*64..+63
    const int m0 = blockIdx.x * 128;

    float* bias_s = reinterpret_cast<float*>(smem);
    if (tid < NTILE) {
        float b = bias0[tid];
        if (bias1) b += bias1[tid];
        bias_s[tid] = b;
    }

    const float ef = (mode == 0) ? 1.0f + *epsPtr : 1.0f;

    float acc[2][8][4];
#pragma unroll
    for (int mt = 0; mt < 2; mt++)
#pragma unroll
        for (int nt = 0; nt < 8; nt++)
#pragma unroll
            for (int j = 0; j < 4; j++) acc[mt][nt][j] = 0.0f;

    for (int kk = 0; kk < K; kk += 128) {
        // ---- B tile via cp.async: NTILE n-rows x 128 k bf16 (hi & lo) ----
#pragma unroll
        for (int it = 0; it < 8; it++) {
            int idx = tid + it * BLOCK;        // 0..NTILE*16-1
            int n = idx >> 4;
            int ch = idx & 15;
            uint32_t off = n * 256 + ((ch ^ (n & 7)) << 4);
            cp16(sb + SMO_BH + off, Bt_hi + (size_t)n * K + kk + ch * 8);
            cp16(sb + SMO_BL + off, Bt_lo + (size_t)n * K + kk + ch * 8);
        }
        asm volatile("cp.async.commit_group;" ::: "memory");

        // ---- A tile: 128 rows x 128 fp32 -> transform -> truncation split ----
#pragma unroll
        for (int it = 0; it < 4096 / BLOCK; it++) {
            int idx = tid + it * BLOCK;        // 0..4095 float4s
            int r = idx >> 5;
            int c4 = (idx & 31) * 4;
            int gr = m0 + r;
            int gk = kk + c4;
            float4 v = make_float4(0.f, 0.f, 0.f, 0.f);
            if (gr < M) {
                if (mode == 0) {
                    float4 a = *reinterpret_cast<const float4*>(A0 + (size_t)gr * 128 + gk);
                    float4 g = *reinterpret_cast<const float4*>(A1 + (size_t)gr * 128 + gk);
                    v.x = fmaf(ef, a.x, g.x); v.y = fmaf(ef, a.y, g.y);
                    v.z = fmaf(ef, a.z, g.z); v.w = fmaf(ef, a.w, g.w);
                } else if (mode == 1) {
                    if (gk < 128) {
                        float4 a = *reinterpret_cast<const float4*>(A0 + (size_t)gr * 128 + gk);
                        float inv = __frcp_rn(fmaxf(aux0[gr], 1.0f));
                        v.x = a.x * inv; v.y = a.y * inv; v.z = a.z * inv; v.w = a.w * inv;
                    } else {
                        v = *reinterpret_cast<const float4*>(A1 + (size_t)gr * 128 + (gk - 128));
                    }
                } else {
                    float4 p = *reinterpret_cast<const float4*>(A0 + (size_t)gr * 256 + gk);
                    float4 q = *reinterpret_cast<const float4*>(A1 + (size_t)gr * 256 + gk);
                    float4 s = *reinterpret_cast<const float4*>(aux0 + gk);
                    float4 hh = *reinterpret_cast<const float4*>(aux1 + gk);
                    v.x = fmaxf(fmaf(p.x, s.x, hh.x), 0.f) + q.x;
                    v.y = fmaxf(fmaf(p.y, s.y, hh.y), 0.f) + q.y;
                    v.z = fmaxf(fmaf(p.z, s.z, hh.z), 0.f) + q.z;
                    v.w = fmaxf(fmaf(p.w, s.w, hh.w), 0.f) + q.w;
                }
            }
            uint32_t bx = __float_as_uint(v.x), by = __float_as_uint(v.y);
            uint32_t bz = __float_as_uint(v.z), bw = __float_as_uint(v.w);
            uint2 hp, lp;
            hp.x = __byte_perm(bx, by, 0x7632);
            hp.y = __byte_perm(bz, bw, 0x7632);
            lp.x = pack_lo_bf16(v.x - __uint_as_float(bx & 0xFFFF0000u),
                                v.y - __uint_as_float(by & 0xFFFF0000u));
            lp.y = pack_lo_bf16(v.z - __uint_as_float(bz & 0xFFFF0000u),
                                v.w - __uint_as_float(bw & 0xFFFF0000u));
            uint32_t off = r * 256 + (((c4 >> 3) ^ (r & 7)) << 4) + ((c4 & 4) << 1);
            *reinterpret_cast<uint2*>(smem + SMO_AH + off) = hp;
            *reinterpret_cast<uint2*>(smem + SMO_AL + off) = lp;
        }
        asm volatile("cp.async.wait_group 0;" ::: "memory");
        __syncthreads();

        // ---- compute: 8 k-steps of 16 ----
        const int arow = wm * 32 + (lid & 15);
        const int akp = lid >> 4;
        const int bn = wn * 64 + (lid & 7) + ((lid >> 4) << 3);
        const int bkp = (lid >> 3) & 1;
#pragma unroll
        for (int ks = 0; ks < 8; ks++) {
            uint32_t ah[2][4], al[2][4];
#pragma unroll
            for (int mt = 0; mt < 2; mt++) {
                int r = arow + mt * 16;
                uint32_t ch = (uint32_t)((ks * 2 + akp) ^ (r & 7));
                uint32_t off = r * 256 + (ch << 4);
                ldm_x4(ah[mt], sb + SMO_AH + off);
                ldm_x4(al[mt], sb + SMO_AL + off);
            }
#pragma unroll
            for (int np = 0; np < 4; np++) {
                int n = bn + np * 16;
                uint32_t ch = (uint32_t)((ks * 2 + bkp) ^ (n & 7));
                uint32_t off = n * 256 + (ch << 4);
                uint32_t bh[4], bl[4];
                ldm_x4(bh, sb + SMO_BH + off);
                ldm_x4(bl, sb + SMO_BL + off);
#pragma unroll
                for (int mt = 0; mt < 2; mt++) {
#pragma unroll
                    for (int sn = 0; sn < 2; sn++) {
                        float* c = acc[mt][np * 2 + sn];
                        mma16816(c, ah[mt], bh + sn * 2);
                        mma16816(c, ah[mt], bl + sn * 2);
                        mma16816(c, al[mt], bh + sn * 2);
                    }
                }
            }
        }
        __syncthreads();
    }

    // ---- epilogue: store + optional fused column stats ----
    const int g = lid >> 2;
    const int tig = lid & 3;
#pragma unroll
    for (int nt = 0; nt < 8; nt++) {
        int nl = wn * 64 + nt * 8 + 2 * tig;
        float b0 = bias_s[nl], b1 = bias_s[nl + 1];
        float s0 = 0.f, s1 = 0.f, q0 = 0.f, q1 = 0.f;
#pragma unroll
        for (int mt = 0; mt < 2; mt++) {
            int m = m0 + wm * 32 + mt * 16 + g;
            if (m < M) {
                float ox = acc[mt][nt][0] + b0, oy = acc[mt][nt][1] + b1;
                *reinterpret_cast<float2*>(C + (size_t)m * ldc + nl) = make_float2(ox, oy);
                s0 += ox; s1 += oy; q0 += ox * ox; q1 += oy * oy;
            }
            if (m + 8 < M) {
                float ox = acc[mt][nt][2] + b0, oy = acc[mt][nt][3] + b1;
                *reinterpret_cast<float2*>(C + (size_t)(m + 8) * ldc + nl) = make_float2(ox, oy);
                s0 += ox; s1 += oy; q0 += ox * ox; q1 += oy * oy;
            }
        }
        if (statsG) {
            // reduce over the 8 lanes (g=0..7) sharing this column pair
#pragma unroll
            for (int d = 4; d < 32; d <<= 1) {
                s0 += __shfl_xor_sync(0xFFFFFFFFu, s0, d);
                s1 += __shfl_xor_sync(0xFFFFFFFFu, s1, d);
                q0 += __shfl_xor_sync(0xFFFFFFFFu, q0, d);
                q1 += __shfl_xor_sync(0xFFFFFFFFu, q1, d);
            }
            if (g == 0) {
                atomicAdd(statsG + nl, s0);
                atomicAdd(statsG + nl + 1, s1);
                atomicAdd(statsG + PD + nl, q0);
                atomicAdd(statsG + PD + nl + 1, q1);
            }
        }
    }
}

// -----------------------------------------------------------------------------------
extern "C" void kernel_launch(void* const* d_in, const int* in_sizes, int n_in,
                              void* d_out, int out_size) {
    const float* x         = (const float*)d_in[0];
    const float* edge_attr = (const float*)d_in[1];
    const float* x_cl      = (const float*)d_in[2];
    const float* c2c_ea    = (const float*)d_in[3];

    int pbase, ebase;
    if (in_sizes[4] == 2 * EA) { ebase = 4; pbase = 8; }
    else                       { pbase = 4; ebase = 26; }

    const int* ei_a   = (const int*)d_in[ebase + 0];
    const int* ei_c2c = (const int*)d_in[ebase + 1];
    const int* ei_a2c = (const int*)d_in[ebase + 2];
    const int* ei_c2a = (const int*)d_in[ebase + 3];

    const float* atom_eps   = (const float*)d_in[pbase + 0];
    const float* atom_W     = (const float*)d_in[pbase + 1];
    const float* atom_b     = (const float*)d_in[pbase + 2];
    const float* atom_gamma = (const float*)d_in[pbase + 3];
    const float* atom_beta  = (const float*)d_in[pbase + 4];
    const float* cl_eps     = (const float*)d_in[pbase + 5];
    const float* cl_W       = (const float*)d_in[pbase + 6];
    const float* cl_b       = (const float*)d_in[pbase + 7];
    const float* cl_gamma   = (const float*)d_in[pbase + 8];
    const float* cl_beta    = (const float*)d_in[pbase + 9];
    const float* a2c_Wl     = (const float*)d_in[pbase + 10];
    const float* a2c_bl     = (const float*)d_in[pbase + 11];
    const float* a2c_Wr     = (const float*)d_in[pbase + 12];
    const float* a2c_br     = (const float*)d_in[pbase + 13];
    const float* c2a_Wl     = (const float*)d_in[pbase + 14];
    const float* c2a_bl     = (const float*)d_in[pbase + 15];
    const float* c2a_Wr     = (const float*)d_in[pbase + 16];
    const float* c2a_br     = (const float*)d_in[pbase + 17];
    const float* merge_atom_W = (const float*)d_in[pbase + 18];
    const float* merge_atom_b = (const float*)d_in[pbase + 19];
    const float* merge_cl_W   = (const float*)d_in[pbase + 20];
    const float* merge_cl_b   = (const float*)d_in[pbase + 21];

    float* out = (float*)d_out;

    float *p_agg_atom, *p_agg_cl, *p_aggm_c2a, *p_cnt_c2a, *p_aggm_a2c, *p_cnt_a2c;
    float *p_pre_atom, *p_pre_cl, *p_S_atom, *p_S_cl;
    float *p_stats_atom, *p_stats_cl, *p_scale_atom, *p_shift_atom, *p_scale_cl, *p_shift_cl;
    __nv_bfloat16 *p_Bt_hi, *p_Bt_lo;
    cudaGetSymbolAddress((void**)&p_agg_atom, g_agg_atom);
    cudaGetSymbolAddress((void**)&p_agg_cl, g_agg_cl);
    cudaGetSymbolAddress((void**)&p_aggm_c2a, g_aggm_c2a);
    cudaGetSymbolAddress((void**)&p_cnt_c2a, g_cnt_c2a);
    cudaGetSymbolAddress((void**)&p_aggm_a2c, g_aggm_a2c);
    cudaGetSymbolAddress((void**)&p_cnt_a2c, g_cnt_a2c);
    cudaGetSymbolAddress((void**)&p_pre_atom, g_pre_atom);
    cudaGetSymbolAddress((void**)&p_pre_cl, g_pre_cl);
    cudaGetSymbolAddress((void**)&p_S_atom, g_S_atom);
    cudaGetSymbolAddress((void**)&p_S_cl, g_S_cl);
    cudaGetSymbolAddress((void**)&p_stats_atom, g_stats_atom);
    cudaGetSymbolAddress((void**)&p_stats_cl, g_stats_cl);
    cudaGetSymbolAddress((void**)&p_scale_atom, g_scale_atom);
    cudaGetSymbolAddress((void**)&p_shift_atom, g_shift_atom);
    cudaGetSymbolAddress((void**)&p_scale_cl, g_scale_cl);
    cudaGetSymbolAddress((void**)&p_shift_cl, g_shift_cl);
    cudaGetSymbolAddress((void**)&p_Bt_hi, g_Bt_hi);
    cudaGetSymbolAddress((void**)&p_Bt_lo, g_Bt_lo);

    cudaMemsetAsync(p_agg_atom, 0, (size_t)NATOM * HD * 4, 0);
    cudaMemsetAsync(p_agg_cl, 0, (size_t)NCL * HD * 4, 0);
    cudaMemsetAsync(p_aggm_c2a, 0, (size_t)NATOM * HD * 4, 0);
    cudaMemsetAsync(p_cnt_c2a, 0, (size_t)NATOM * 4, 0);
    cudaMemsetAsync(p_aggm_a2c, 0, (size_t)NCL * HD * 4, 0);
    cudaMemsetAsync(p_cnt_a2c, 0, (size_t)NCL * 4, 0);
    cudaMemsetAsync(p_stats_atom, 0, 2 * PD * 4, 0);
    cudaMemsetAsync(p_stats_cl, 0, 2 * PD * 4, 0);

    const int SMEM_256 = 66560 + 256 * 256 * 2;  // 197632
    const int SMEM_128 = 66560 + 128 * 256 * 2;  // 132096
    cudaFuncSetAttribute((const void*)hmma_gemm<128, 256>,
                         cudaFuncAttributeMaxDynamicSharedMemorySize, SMEM_256);
    cudaFuncSetAttribute((const void*)hmma_gemm<256, 256>,
                         cudaFuncAttributeMaxDynamicSharedMemorySize, SMEM_256);
    cudaFuncSetAttribute((const void*)hmma_gemm<256, 128>,
                         cudaFuncAttributeMaxDynamicSharedMemorySize, SMEM_128);

    // ---- fused weight transpose + split (one launch) ----
    {
        WsplitArgs wa;
        wa.src[0] = atom_W;  wa.src[1] = cl_W;
        wa.src[2] = c2a_Wl;  wa.src[3] = c2a_Wr;
        wa.src[4] = a2c_Wl;  wa.src[5] = a2c_Wr;
        wa.src[6] = merge_atom_W; wa.src[7] = merge_cl_W;
        wsplit_all<<<1024, 256>>>(wa, p_Bt_hi, p_Bt_lo);
    }

    // ---- scatter passes ----
    gine_scatter<<<(EA * 32 + 255) / 256, 256>>>(x, edge_attr, ei_a, EA, p_agg_atom);
    gine_scatter<<<(EC * 32 + 255) / 256, 256>>>(x_cl, c2c_ea, ei_c2c, EC, p_agg_cl);
    sage_scatter<<<(EB * 32 + 255) / 256, 256>>>(x, ei_a2c, EB, p_aggm_a2c, p_cnt_a2c);
    sage_scatter<<<(EB * 32 + 255) / 256, 256>>>(x_cl, ei_c2a, EB, p_aggm_c2a, p_cnt_c2a);

    const int GA = (NATOM + 127) / 128;  // 782
    const int GC = (NCL + 127) / 128;    // 196

    // ---- GINE GEMMs (pre-BN, fused column stats): [M,128]@[128,256] ----
    hmma_gemm<128, 256><<<GA, 512, SMEM_256>>>(
        0, NATOM, x, p_agg_atom, nullptr, nullptr,
        p_Bt_hi + OFF_GA, p_Bt_lo + OFF_GA, atom_b, nullptr, atom_eps, p_stats_atom,
        p_pre_atom, 256);
    hmma_gemm<128, 256><<<GC, 512, SMEM_256>>>(
        0, NCL, x_cl, p_agg_cl, nullptr, nullptr,
        p_Bt_hi + OFF_GC, p_Bt_lo + OFF_GC, cl_b, nullptr, cl_eps, p_stats_cl,
        p_pre_cl, 256);

    bn_finalize<<<1, 256>>>(p_stats_atom, atom_gamma, atom_beta, 1.0f / NATOM,
                            p_scale_atom, p_shift_atom);
    bn_finalize<<<1, 256>>>(p_stats_cl, cl_gamma, cl_beta, 1.0f / NCL,
                            p_scale_cl, p_shift_cl);

    // ---- SAGE GEMMs: [mean | x_dst]@[Wl;Wr]+bl+br -> [M,256] ----
    hmma_gemm<256, 256><<<GA, 512, SMEM_256>>>(
        1, NATOM, p_aggm_c2a, x, p_cnt_c2a, nullptr,
        p_Bt_hi + OFF_SA, p_Bt_lo + OFF_SA, c2a_bl, c2a_br, nullptr, nullptr,
        p_S_atom, 256);
    hmma_gemm<256, 256><<<GC, 512, SMEM_256>>>(
        1, NCL, p_aggm_a2c, x_cl, p_cnt_a2c, nullptr,
        p_Bt_hi + OFF_SC, p_Bt_lo + OFF_SC, a2c_bl, a2c_br, nullptr, nullptr,
        p_S_cl, 256);

    // ---- merge GEMMs (fused BN+ReLU+residual) -> final output [M,128] ----
    hmma_gemm<256, 128><<<GA, 256, SMEM_128>>>(
        2, NATOM, p_pre_atom, p_S_atom, p_scale_atom, p_shift_atom,
        p_Bt_hi + OFF_MA, p_Bt_lo + OFF_MA, merge_atom_b, nullptr, nullptr, nullptr,
        out, 128);
    hmma_gemm<256, 128><<<GC, 256, SMEM_128>>>(
        2, NCL, p_pre_cl, p_S_cl, p_scale_cl, p_shift_cl,
        p_Bt_hi + OFF_MC, p_Bt_lo + OFF_MC, merge_cl_b, nullptr, nullptr, nullptr,
        out + (size_t)NATOM * HD, 128);
}